// round 13
// baseline (speedup 1.0000x reference)
#include <cuda_runtime.h>
#include <cuda_bf16.h>
#include <math.h>
#include <float.h>
#include <stdint.h>

#define BSZ 2
#define SEQ 2048
#define HIDN 2048
#define NHEAD 16
#define NKVH 4
#define HDIM 128
#define NREP (NHEAD / NKVH)
#define QKVN (HIDN + 2 * NKVH * HDIM) /* 3072 */
#define MROWS (BSZ * SEQ)             /* 4096 */

// ---------------------------------------------------------------------------
// Scratch (static device globals; no runtime allocation allowed)
// ---------------------------------------------------------------------------
__device__ float g_qkv[(size_t)MROWS * QKVN];

__device__ __nv_bfloat16 g_hs_hi[(size_t)MROWS * HIDN];
__device__ __nv_bfloat16 g_hs_lo[(size_t)MROWS * HIDN];
__device__ __nv_bfloat16 g_wqkv_hi[(size_t)QKVN * HIDN];
__device__ __nv_bfloat16 g_wqkv_lo[(size_t)QKVN * HIDN];
__device__ __nv_bfloat16 g_wout_hi[(size_t)HIDN * HIDN];
__device__ __nv_bfloat16 g_wout_lo[(size_t)HIDN * HIDN];
__device__ __nv_bfloat16 g_ctx_hi[(size_t)MROWS * HIDN];
__device__ __nv_bfloat16 g_ctx_lo[(size_t)MROWS * HIDN];

__device__ __nv_bfloat16 g_q_hi[(size_t)BSZ * NHEAD * SEQ * HDIM];
__device__ __nv_bfloat16 g_q_lo[(size_t)BSZ * NHEAD * SEQ * HDIM];
__device__ __nv_bfloat16 g_k_hi[(size_t)BSZ * NKVH * SEQ * HDIM];
__device__ __nv_bfloat16 g_k_lo[(size_t)BSZ * NKVH * SEQ * HDIM];
// V pre-transposed: [b][hk][d][SEQ]
__device__ __nv_bfloat16 g_vt_hi[(size_t)BSZ * NKVH * HDIM * SEQ];
__device__ __nv_bfloat16 g_vt_lo[(size_t)BSZ * NKVH * HDIM * SEQ];

// ---------------------------------------------------------------------------
// Portable tensor-core primitives (baseline PTX, valid on plain sm_103)
// ---------------------------------------------------------------------------
__device__ __forceinline__ uint32_t smem_u32(const void* p) {
    uint32_t a;
    asm("{ .reg .u64 t; cvta.to.shared.u64 t, %1; cvt.u32.u64 %0, t; }"
        : "=r"(a) : "l"(p));
    return a;
}

#define LDSM_X4(r0, r1, r2, r3, addr)                                          \
    asm volatile(                                                              \
        "ldmatrix.sync.aligned.m8n8.x4.shared.b16 {%0,%1,%2,%3}, [%4];"        \
        : "=r"(r0), "=r"(r1), "=r"(r2), "=r"(r3) : "r"(addr))

#define MMA16816(c, a, b)                                                      \
    asm volatile(                                                              \
        "mma.sync.aligned.m16n8k16.row.col.f32.bf16.bf16.f32 "                 \
        "{%0,%1,%2,%3}, {%4,%5,%6,%7}, {%8,%9}, {%0,%1,%2,%3};"                \
        : "+f"((c)[0]), "+f"((c)[1]), "+f"((c)[2]), "+f"((c)[3])               \
        : "r"((a)[0]), "r"((a)[1]), "r"((a)[2]), "r"((a)[3]),                  \
          "r"((b)[0]), "r"((b)[1]))

#define CP_ASYNC16(dst, src)                                                   \
    asm volatile("cp.async.cg.shared.global [%0], [%1], 16;"                   \
                 :: "r"(dst), "l"(src) : "memory")
#define CP_COMMIT() asm volatile("cp.async.commit_group;" ::: "memory")
#define CP_WAIT(n) asm volatile("cp.async.wait_group %0;" :: "n"(n) : "memory")

__device__ __forceinline__ void split2(float x, float y, uint32_t& hi,
                                       uint32_t& lo) {
    __nv_bfloat16 hx = __float2bfloat16(x), hy = __float2bfloat16(y);
    __nv_bfloat16 lx = __float2bfloat16(x - __bfloat162float(hx));
    __nv_bfloat16 ly = __float2bfloat16(y - __bfloat162float(hy));
    __nv_bfloat162 h2 = __halves2bfloat162(hx, hy);
    __nv_bfloat162 l2 = __halves2bfloat162(lx, ly);
    hi = *(uint32_t*)&h2;
    lo = *(uint32_t*)&l2;
}

// ---------------------------------------------------------------------------
// fp32 -> (bf16 hi, bf16 lo) split, 4 elems/thread
// ---------------------------------------------------------------------------
__global__ void split_kernel(const float4* __restrict__ src,
                             __nv_bfloat162* __restrict__ hi,
                             __nv_bfloat162* __restrict__ lo, int n4) {
    int i = blockIdx.x * blockDim.x + threadIdx.x;
    if (i >= n4) return;
    float4 x = src[i];
    uint32_t h0, l0, h1, l1;
    split2(x.x, x.y, h0, l0);
    split2(x.z, x.w, h1, l1);
    ((uint32_t*)hi)[2 * i] = h0;
    ((uint32_t*)hi)[2 * i + 1] = h1;
    ((uint32_t*)lo)[2 * i] = l0;
    ((uint32_t*)lo)[2 * i + 1] = l1;
}

// ---------------------------------------------------------------------------
// bf16x3 HMMA GEMM v4 (unchanged from R12 — at HMMA hw rate, frozen)
// ---------------------------------------------------------------------------
#define SROW2 80
#define TILE2 (128 * SROW2)
#define STAGE2 (4 * TILE2)
#define GEMM2_SMEM (2 * STAGE2)

template <int N, int K>
__global__ __launch_bounds__(128) void gemm_hmma4(
    const __nv_bfloat16* __restrict__ a_hi, const __nv_bfloat16* __restrict__ a_lo,
    const __nv_bfloat16* __restrict__ w_hi, const __nv_bfloat16* __restrict__ w_lo,
    float* __restrict__ C) {
    constexpr int NCH = K / 32;

    extern __shared__ __align__(16) char sm2[];
    const uint32_t sb = smem_u32(sm2);

    const int tid = threadIdx.x;
    const int lane = tid & 31;
    const int warp = tid >> 5;
    const int wm = warp >> 1;
    const int wn = warp & 1;
    const int m0 = blockIdx.y * 128;
    const int n0 = blockIdx.x * 128;

    auto stage_load = [&](int buf, int kk) {
        const uint32_t dst = sb + buf * STAGE2;
#pragma unroll
        for (int i = 0; i < 4; i++) {
            int lin = tid + i * 128;
            int row = lin >> 2;
            int c16 = lin & 3;
            uint32_t so = (uint32_t)row * SROW2 + c16 * 16;
            size_t ga = (size_t)(m0 + row) * K + kk + c16 * 8;
            size_t gw = (size_t)(n0 + row) * K + kk + c16 * 8;
            CP_ASYNC16(dst + 0 * TILE2 + so, a_hi + ga);
            CP_ASYNC16(dst + 1 * TILE2 + so, a_lo + ga);
            CP_ASYNC16(dst + 2 * TILE2 + so, w_hi + gw);
            CP_ASYNC16(dst + 3 * TILE2 + so, w_lo + gw);
        }
    };

    float acc[4][8][4];
#pragma unroll
    for (int t = 0; t < 4; t++)
#pragma unroll
        for (int n = 0; n < 8; n++)
#pragma unroll
            for (int j = 0; j < 4; j++) acc[t][n][j] = 0.0f;

    const uint32_t a_row = (uint32_t)(wm * 64 + ((lane >> 3) & 1) * 8 + (lane & 7));
    const uint32_t a_cb = (uint32_t)((lane >> 4) & 1) * 16;
    const uint32_t b_row = (uint32_t)(wn * 64 + ((lane >> 4) & 1) * 8 + (lane & 7));
    const uint32_t b_cb = (uint32_t)((lane >> 3) & 1) * 16;

    stage_load(0, 0);
    CP_COMMIT();

#pragma unroll 1
    for (int c = 0; c < NCH; c++) {
        if (c + 1 < NCH) {
            stage_load((c + 1) & 1, (c + 1) * 32);
            CP_COMMIT();
            CP_WAIT(1);
        } else {
            CP_WAIT(0);
        }
        __syncthreads();

        const uint32_t st = sb + (c & 1) * STAGE2;
        const uint32_t sAhi = st, sAlo = st + TILE2;
        const uint32_t sWhi = st + 2 * TILE2, sWlo = st + 3 * TILE2;

#pragma unroll
        for (int k16 = 0; k16 < 2; k16++) {
            const uint32_t kb = (uint32_t)k16 * 32;
            uint32_t ah[4][4], al[4][4];
#pragma unroll
            for (int t = 0; t < 4; t++) {
                LDSM_X4(ah[t][0], ah[t][1], ah[t][2], ah[t][3],
                        sAhi + (a_row + t * 16) * SROW2 + kb + a_cb);
                LDSM_X4(al[t][0], al[t][1], al[t][2], al[t][3],
                        sAlo + (a_row + t * 16) * SROW2 + kb + a_cb);
            }
            uint32_t bh[8][2], bl[8][2];
#pragma unroll
            for (int p = 0; p < 4; p++) {
                uint32_t r0, r1, r2, r3;
                LDSM_X4(r0, r1, r2, r3,
                        sWhi + (b_row + p * 16) * SROW2 + kb + b_cb);
                bh[2 * p][0] = r0; bh[2 * p][1] = r1;
                bh[2 * p + 1][0] = r2; bh[2 * p + 1][1] = r3;
                LDSM_X4(r0, r1, r2, r3,
                        sWlo + (b_row + p * 16) * SROW2 + kb + b_cb);
                bl[2 * p][0] = r0; bl[2 * p][1] = r1;
                bl[2 * p + 1][0] = r2; bl[2 * p + 1][1] = r3;
            }
#pragma unroll
            for (int t = 0; t < 4; t++)
#pragma unroll
                for (int n = 0; n < 8; n++) MMA16816(acc[t][n], ah[t], bh[n]);
#pragma unroll
            for (int t = 0; t < 4; t++)
#pragma unroll
                for (int n = 0; n < 8; n++) MMA16816(acc[t][n], al[t], bh[n]);
#pragma unroll
            for (int t = 0; t < 4; t++)
#pragma unroll
                for (int n = 0; n < 8; n++) MMA16816(acc[t][n], ah[t], bl[n]);
        }
        __syncthreads();
    }

#pragma unroll
    for (int t = 0; t < 4; t++) {
        int r0 = m0 + wm * 64 + t * 16 + (lane >> 2);
#pragma unroll
        for (int n = 0; n < 8; n++) {
            int col = n0 + wn * 64 + n * 8 + (lane & 3) * 2;
            *(float2*)&C[(size_t)r0 * N + col] = make_float2(acc[t][n][0], acc[t][n][1]);
            *(float2*)&C[(size_t)(r0 + 8) * N + col] = make_float2(acc[t][n][2], acc[t][n][3]);
        }
    }
}

// ---------------------------------------------------------------------------
// Position read: robust to int32 vs int64 storage of position_ids (arange).
// ---------------------------------------------------------------------------
__device__ __forceinline__ int read_pos(const int* __restrict__ pos32, int n) {
    bool is64 = (pos32[1] == 0);
    return pos32[is64 ? 2 * n : n];
}

// RoPE + scatter + bf16 hi/lo split
__global__ void rope_q_kernel(const int* __restrict__ pos32) {
    int idx = blockIdx.x * blockDim.x + threadIdx.x;
    int d = idx & 63;
    int h = (idx >> 6) & (NHEAD - 1);
    int s = (idx >> 10) & (SEQ - 1);
    int b = idx >> 21;

    int p = read_pos(pos32, b * SEQ + s);
    float invf = (float)exp(-((double)d / 64.0) * 9.210340371976184);
    float ang = (float)p * invf;
    float sn, c;
    sincosf(ang, &sn, &c);

    const float* src = g_qkv + ((size_t)b * SEQ + s) * QKVN + h * HDIM;
    float x1 = src[d], x2 = src[d + 64];
    float y1 = x1 * c - x2 * sn;
    float y2 = x2 * c + x1 * sn;

    size_t o = (((size_t)(b * NHEAD + h)) * SEQ + s) * HDIM;
    __nv_bfloat16 h1 = __float2bfloat16(y1);
    __nv_bfloat16 h2 = __float2bfloat16(y2);
    g_q_hi[o + d] = h1;
    g_q_hi[o + d + 64] = h2;
    g_q_lo[o + d] = __float2bfloat16(y1 - __bfloat162float(h1));
    g_q_lo[o + d + 64] = __float2bfloat16(y2 - __bfloat162float(h2));
}

__global__ void rope_k_kernel(const int* __restrict__ pos32) {
    int idx = blockIdx.x * blockDim.x + threadIdx.x;
    int d = idx & 63;
    int h = (idx >> 6) & (NKVH - 1);
    int s = (idx >> 8) & (SEQ - 1);
    int b = idx >> 19;

    int p = read_pos(pos32, b * SEQ + s);
    float invf = (float)exp(-((double)d / 64.0) * 9.210340371976184);
    float ang = (float)p * invf;
    float sn, c;
    sincosf(ang, &sn, &c);

    const float* src = g_qkv + ((size_t)b * SEQ + s) * QKVN + HIDN + h * HDIM;
    float x1 = src[d], x2 = src[d + 64];
    float y1 = x1 * c - x2 * sn;
    float y2 = x2 * c + x1 * sn;

    size_t o = (((size_t)(b * NKVH + h)) * SEQ + s) * HDIM;
    __nv_bfloat16 h1 = __float2bfloat16(y1);
    __nv_bfloat16 h2 = __float2bfloat16(y2);
    g_k_hi[o + d] = h1;
    g_k_hi[o + d + 64] = h2;
    g_k_lo[o + d] = __float2bfloat16(y1 - __bfloat162float(h1));
    g_k_lo[o + d + 64] = __float2bfloat16(y2 - __bfloat162float(h2));
}

// ---------------------------------------------------------------------------
// V split + transpose to [b][hk][d][SEQ].
// ---------------------------------------------------------------------------
__global__ void vt_split_kernel() {
    __shared__ __nv_bfloat16 thi[32][72];
    __shared__ __nv_bfloat16 tlo[32][72];
    const int s0 = blockIdx.x * 64;
    const int hk = blockIdx.y >> 2;
    const int d0 = (blockIdx.y & 3) * 32;
    const int b = blockIdx.z;
    const int t = threadIdx.x;

#pragma unroll
    for (int i = 0; i < 8; i++) {
        int s = (t >> 5) + i * 8;
        int d = t & 31;
        float x = g_qkv[((size_t)b * SEQ + s0 + s) * QKVN + HIDN + NKVH * HDIM +
                        hk * HDIM + d0 + d];
        __nv_bfloat16 h = __float2bfloat16(x);
        thi[d][s] = h;
        tlo[d][s] = __float2bfloat16(x - __bfloat162float(h));
    }
    __syncthreads();

    int d = t >> 3, c8 = (t & 7) * 8;
    size_t o = (((size_t)(b * NKVH + hk)) * HDIM + d0 + d) * SEQ + s0 + c8;
    *(uint4*)(g_vt_hi + o) = *(uint4*)&thi[d][c8];
    *(uint4*)(g_vt_lo + o) = *(uint4*)&tlo[d][c8];
}

// ---------------------------------------------------------------------------
// Flash attention via HMMA bf16x3: BQ=128, BK=64, 256 threads (8 warps x
// 16 q-rows). Per k-tile K/V traffic amortized over 2x the MMA work.
// ---------------------------------------------------------------------------
#define QS_STR 272
#define VT_STR 144
#define ATTN_SMEM (2 * 128 * QS_STR + 2 * 64 * QS_STR + 2 * 128 * VT_STR) /* 141312 */

__global__ __launch_bounds__(256, 1) void attn_hmma() {
    extern __shared__ __align__(16) char smr[];
    const uint32_t sbase = smem_u32(smr);
    const uint32_t sQhi = sbase;
    const uint32_t sQlo = sQhi + 128 * QS_STR;
    const uint32_t sKhi = sQlo + 128 * QS_STR;
    const uint32_t sKlo = sKhi + 64 * QS_STR;
    const uint32_t sVhi = sKlo + 64 * QS_STR;
    const uint32_t sVlo = sVhi + 128 * VT_STR;
    char* cQhi = smr;
    char* cQlo = smr + 128 * QS_STR;

    const int tid = threadIdx.x;
    const int lane = tid & 31;
    const int wm = tid >> 5; // 0..7
    const int qb2 = gridDim.x - 1 - blockIdx.x; // heaviest first
    const int h = blockIdx.y;
    const int b = blockIdx.z;
    const int q0 = qb2 * 128;
    const int hk = h / NREP;

    const __nv_bfloat16* Qhig = g_q_hi + (((size_t)(b * NHEAD + h)) * SEQ + q0) * HDIM;
    const __nv_bfloat16* Qlog = g_q_lo + (((size_t)(b * NHEAD + h)) * SEQ + q0) * HDIM;
    const __nv_bfloat16* Khig = g_k_hi + ((size_t)(b * NKVH + hk)) * SEQ * HDIM;
    const __nv_bfloat16* Klog = g_k_lo + ((size_t)(b * NKVH + hk)) * SEQ * HDIM;
    const __nv_bfloat16* Vthig = g_vt_hi + ((size_t)(b * NKVH + hk)) * HDIM * SEQ;
    const __nv_bfloat16* Vtlog = g_vt_lo + ((size_t)(b * NKVH + hk)) * HDIM * SEQ;

    // Q tiles: 128 rows x 128 bf16 (hi+lo)
#pragma unroll
    for (int i = 0; i < 8; i++) {
        int lin = tid + i * 256;
        int row = lin >> 4, c = lin & 15;
        *(uint4*)(cQhi + row * QS_STR + c * 16) =
            *(const uint4*)(Qhig + (size_t)row * HDIM + c * 8);
        *(uint4*)(cQlo + row * QS_STR + c * 16) =
            *(const uint4*)(Qlog + (size_t)row * HDIM + c * 8);
    }
    __syncthreads();

    const uint32_t a_row = (uint32_t)(wm * 16 + ((lane >> 3) & 1) * 8 + (lane & 7));
    const uint32_t a_cb = (uint32_t)((lane >> 4) & 1) * 16;
    const uint32_t b_row = (uint32_t)(((lane >> 4) & 1) * 8 + (lane & 7));
    const uint32_t b_cb = (uint32_t)((lane >> 3) & 1) * 16;

    uint32_t qhi[8][4], qlo[8][4];
#pragma unroll
    for (int k16 = 0; k16 < 8; k16++) {
        LDSM_X4(qhi[k16][0], qhi[k16][1], qhi[k16][2], qhi[k16][3],
                sQhi + a_row * QS_STR + k16 * 32 + a_cb);
        LDSM_X4(qlo[k16][0], qlo[k16][1], qlo[k16][2], qlo[k16][3],
                sQlo + a_row * QS_STR + k16 * 32 + a_cb);
    }

    float o[16][4];
#pragma unroll
    for (int n = 0; n < 16; n++)
#pragma unroll
        for (int j = 0; j < 4; j++) o[n][j] = 0.0f;
    float m0r = -FLT_MAX, m1r = -FLT_MAX, l0 = 0.0f, l1 = 0.0f;

    const float scale = 0.08838834764831845f;
    const int rowg0 = q0 + wm * 16 + (lane >> 2);
    const int rowg1 = rowg0 + 8;
    const int ktiles = 2 * qb2 + 2;

#pragma unroll 1
    for (int kt = 0; kt < ktiles; kt++) {
        const int k0 = kt * 64;
        __syncthreads(); // previous iteration's smem reads complete

        // K tiles (64 x 128 bf16, hi+lo) via cp.async: 4 iters x 256 thr
#pragma unroll
        for (int i = 0; i < 4; i++) {
            int lin = tid + i * 256;
            int row = lin >> 4, c = lin & 15;
            uint32_t so = (uint32_t)row * QS_STR + c * 16;
            size_t go = (size_t)(k0 + row) * HDIM + c * 8;
            CP_ASYNC16(sKhi + so, Khig + go);
            CP_ASYNC16(sKlo + so, Klog + go);
        }
        // Vt tiles (128 d-rows x 64 k, hi+lo): 4 iters x 256 thr
#pragma unroll
        for (int i = 0; i < 4; i++) {
            int lin = tid + i * 256;
            int row = lin >> 3, c = lin & 7;
            uint32_t so = (uint32_t)row * VT_STR + c * 16;
            size_t go = (size_t)row * SEQ + k0 + c * 8;
            CP_ASYNC16(sVhi + so, Vthig + go);
            CP_ASYNC16(sVlo + so, Vtlog + go);
        }
        CP_COMMIT();
        CP_WAIT(0);
        __syncthreads();

        // ---- S = Q K^T (bf16x3) ----
        float s[8][4];
#pragma unroll
        for (int n = 0; n < 8; n++)
#pragma unroll
            for (int j = 0; j < 4; j++) s[n][j] = 0.0f;

#pragma unroll
        for (int k16 = 0; k16 < 8; k16++) {
            uint32_t bh[8][2], bl[8][2];
#pragma unroll
            for (int p = 0; p < 4; p++) {
                uint32_t r0, r1, r2, r3;
                LDSM_X4(r0, r1, r2, r3,
                        sKhi + (p * 16 + b_row) * QS_STR + k16 * 32 + b_cb);
                bh[2 * p][0] = r0; bh[2 * p][1] = r1;
                bh[2 * p + 1][0] = r2; bh[2 * p + 1][1] = r3;
                LDSM_X4(r0, r1, r2, r3,
                        sKlo + (p * 16 + b_row) * QS_STR + k16 * 32 + b_cb);
                bl[2 * p][0] = r0; bl[2 * p][1] = r1;
                bl[2 * p + 1][0] = r2; bl[2 * p + 1][1] = r3;
            }
#pragma unroll
            for (int n = 0; n < 8; n++) MMA16816(s[n], qhi[k16], bh[n]);
#pragma unroll
            for (int n = 0; n < 8; n++) MMA16816(s[n], qlo[k16], bh[n]);
#pragma unroll
            for (int n = 0; n < 8; n++) MMA16816(s[n], qhi[k16], bl[n]);
        }

        // ---- scale + causal mask (diagonal region: k0 >= q0) ----
#pragma unroll
        for (int n = 0; n < 8; n++)
#pragma unroll
            for (int j = 0; j < 4; j++) s[n][j] *= scale;
        if (k0 >= q0) {
            const int colb = k0 + (lane & 3) * 2;
#pragma unroll
            for (int n = 0; n < 8; n++) {
#pragma unroll
                for (int e = 0; e < 2; e++) {
                    int col = colb + n * 8 + e;
                    if (col > rowg0) s[n][e] = -1e30f;
                    if (col > rowg1) s[n][2 + e] = -1e30f;
                }
            }
        }

        // ---- online softmax (registers + quad shfl) ----
        float mx0 = -FLT_MAX, mx1 = -FLT_MAX;
#pragma unroll
        for (int n = 0; n < 8; n++) {
            mx0 = fmaxf(mx0, fmaxf(s[n][0], s[n][1]));
            mx1 = fmaxf(mx1, fmaxf(s[n][2], s[n][3]));
        }
        mx0 = fmaxf(mx0, __shfl_xor_sync(0xffffffffu, mx0, 1));
        mx0 = fmaxf(mx0, __shfl_xor_sync(0xffffffffu, mx0, 2));
        mx1 = fmaxf(mx1, __shfl_xor_sync(0xffffffffu, mx1, 1));
        mx1 = fmaxf(mx1, __shfl_xor_sync(0xffffffffu, mx1, 2));
        float mn0 = fmaxf(m0r, mx0), mn1 = fmaxf(m1r, mx1);
        float corr0 = __expf(m0r - mn0), corr1 = __expf(m1r - mn1);
        m0r = mn0; m1r = mn1;

        float rs0 = 0.0f, rs1 = 0.0f;
#pragma unroll
        for (int n = 0; n < 8; n++) {
            s[n][0] = __expf(s[n][0] - mn0);
            s[n][1] = __expf(s[n][1] - mn0);
            s[n][2] = __expf(s[n][2] - mn1);
            s[n][3] = __expf(s[n][3] - mn1);
            rs0 += s[n][0] + s[n][1];
            rs1 += s[n][2] + s[n][3];
        }
        rs0 += __shfl_xor_sync(0xffffffffu, rs0, 1);
        rs0 += __shfl_xor_sync(0xffffffffu, rs0, 2);
        rs1 += __shfl_xor_sync(0xffffffffu, rs1, 1);
        rs1 += __shfl_xor_sync(0xffffffffu, rs1, 2);
        l0 = l0 * corr0 + rs0;
        l1 = l1 * corr1 + rs1;

#pragma unroll
        for (int n = 0; n < 16; n++) {
            o[n][0] *= corr0; o[n][1] *= corr0;
            o[n][2] *= corr1; o[n][3] *= corr1;
        }

        // ---- O += P V (bf16x3), P frags straight from S regs ----
#pragma unroll
        for (int j = 0; j < 4; j++) {
            uint32_t ah[4], al[4];
            split2(s[2 * j][0], s[2 * j][1], ah[0], al[0]);
            split2(s[2 * j][2], s[2 * j][3], ah[1], al[1]);
            split2(s[2 * j + 1][0], s[2 * j + 1][1], ah[2], al[2]);
            split2(s[2 * j + 1][2], s[2 * j + 1][3], ah[3], al[3]);
#pragma unroll
            for (int p = 0; p < 8; p++) {
                uint32_t r0, r1, r2, r3, u0, u1, u2, u3;
                LDSM_X4(r0, r1, r2, r3,
                        sVhi + (p * 16 + b_row) * VT_STR + j * 32 + b_cb);
                LDSM_X4(u0, u1, u2, u3,
                        sVlo + (p * 16 + b_row) * VT_STR + j * 32 + b_cb);
                uint32_t bh0[2] = {r0, r1}, bh1[2] = {r2, r3};
                uint32_t bl0[2] = {u0, u1}, bl1[2] = {u2, u3};
                MMA16816(o[2 * p], ah, bh0);
                MMA16816(o[2 * p + 1], ah, bh1);
                MMA16816(o[2 * p], al, bh0);
                MMA16816(o[2 * p + 1], al, bh1);
                MMA16816(o[2 * p], ah, bl0);
                MMA16816(o[2 * p + 1], ah, bl1);
            }
        }
    }

    // ---- epilogue: normalize, split hi/lo, write [b, s, h, d] ----
    float linv0 = 1.0f / l0, linv1 = 1.0f / l1;
    size_t base0 = (((size_t)b * SEQ + rowg0) * NHEAD + h) * HDIM + (lane & 3) * 2;
    size_t base1 = (((size_t)b * SEQ + rowg1) * NHEAD + h) * HDIM + (lane & 3) * 2;
#pragma unroll
    for (int n = 0; n < 16; n++) {
        uint32_t hi, lo;
        split2(o[n][0] * linv0, o[n][1] * linv0, hi, lo);
        *(uint32_t*)(g_ctx_hi + base0 + n * 8) = hi;
        *(uint32_t*)(g_ctx_lo + base0 + n * 8) = lo;
        split2(o[n][2] * linv1, o[n][3] * linv1, hi, lo);
        *(uint32_t*)(g_ctx_hi + base1 + n * 8) = hi;
        *(uint32_t*)(g_ctx_lo + base1 + n * 8) = lo;
    }
}

// ---------------------------------------------------------------------------
extern "C" void kernel_launch(void* const* d_in, const int* in_sizes, int n_in,
                              void* d_out, int out_size) {
    const float* hs = (const float*)d_in[0];
    const float* w_qkv = (const float*)d_in[1];
    const float* w_out = (const float*)d_in[2];
    const int* pos32 = (const int*)d_in[4];
    float* out = (float*)d_out;

    float* qkv;
    __nv_bfloat16 *hs_hi, *hs_lo, *wq_hi, *wq_lo, *wo_hi, *wo_lo, *cx_hi, *cx_lo;
    cudaGetSymbolAddress((void**)&qkv, g_qkv);
    cudaGetSymbolAddress((void**)&hs_hi, g_hs_hi);
    cudaGetSymbolAddress((void**)&hs_lo, g_hs_lo);
    cudaGetSymbolAddress((void**)&wq_hi, g_wqkv_hi);
    cudaGetSymbolAddress((void**)&wq_lo, g_wqkv_lo);
    cudaGetSymbolAddress((void**)&wo_hi, g_wout_hi);
    cudaGetSymbolAddress((void**)&wo_lo, g_wout_lo);
    cudaGetSymbolAddress((void**)&cx_hi, g_ctx_hi);
    cudaGetSymbolAddress((void**)&cx_lo, g_ctx_lo);

    cudaFuncSetAttribute(gemm_hmma4<QKVN, HIDN>,
                         cudaFuncAttributeMaxDynamicSharedMemorySize, GEMM2_SMEM);
    cudaFuncSetAttribute(gemm_hmma4<HIDN, HIDN>,
                         cudaFuncAttributeMaxDynamicSharedMemorySize, GEMM2_SMEM);
    cudaFuncSetAttribute(attn_hmma, cudaFuncAttributeMaxDynamicSharedMemorySize,
                         ATTN_SMEM);

    // 0. bf16 hi/lo splits of inputs
    {
        int n4;
        n4 = (MROWS * HIDN) / 4;
        split_kernel<<<(n4 + 255) / 256, 256>>>((const float4*)hs,
                                                (__nv_bfloat162*)hs_hi,
                                                (__nv_bfloat162*)hs_lo, n4);
        n4 = (QKVN * HIDN) / 4;
        split_kernel<<<(n4 + 255) / 256, 256>>>((const float4*)w_qkv,
                                                (__nv_bfloat162*)wq_hi,
                                                (__nv_bfloat162*)wq_lo, n4);
        n4 = (HIDN * HIDN) / 4;
        split_kernel<<<(n4 + 255) / 256, 256>>>((const float4*)w_out,
                                                (__nv_bfloat162*)wo_hi,
                                                (__nv_bfloat162*)wo_lo, n4);
    }

    // 1. QKV GEMM (HMMA bf16x3)
    {
        dim3 grid(QKVN / 128, MROWS / 128);
        gemm_hmma4<QKVN, HIDN><<<grid, 128, GEMM2_SMEM>>>(hs_hi, hs_lo, wq_hi,
                                                          wq_lo, qkv);
    }

    // 2. RoPE + scatter; V split+transpose
    rope_q_kernel<<<(BSZ * SEQ * NHEAD * 64) / 256, 256>>>(pos32);
    rope_k_kernel<<<(BSZ * SEQ * NKVH * 64) / 256, 256>>>(pos32);
    {
        dim3 grid(SEQ / 64, (HDIM / 32) * NKVH, BSZ);
        vt_split_kernel<<<grid, 256>>>();
    }

    // 3. Flash attention (HMMA bf16x3, BQ=128)
    {
        dim3 grid(SEQ / 128, NHEAD, BSZ);
        attn_hmma<<<grid, 256, ATTN_SMEM>>>();
    }

    // 4. Output GEMM (HMMA bf16x3)
    {
        dim3 grid(HIDN / 128, MROWS / 128);
        gemm_hmma4<HIDN, HIDN><<<grid, 128, GEMM2_SMEM>>>(cx_hi, cx_lo, wo_hi,
                                                          wo_lo, out);
    }
}

// round 14
// speedup vs baseline: 1.0310x; 1.0310x over previous
#include <cuda_runtime.h>
#include <cuda_bf16.h>
#include <math.h>
#include <float.h>
#include <stdint.h>

#define BSZ 2
#define SEQ 2048
#define HIDN 2048
#define NHEAD 16
#define NKVH 4
#define HDIM 128
#define NREP (NHEAD / NKVH)
#define QKVN (HIDN + 2 * NKVH * HDIM) /* 3072 */
#define MROWS (BSZ * SEQ)             /* 4096 */

// ---------------------------------------------------------------------------
// Scratch (static device globals; no runtime allocation allowed)
// ---------------------------------------------------------------------------
__device__ float g_qkv[(size_t)MROWS * QKVN];

__device__ __nv_bfloat16 g_hs_hi[(size_t)MROWS * HIDN];
__device__ __nv_bfloat16 g_hs_lo[(size_t)MROWS * HIDN];
__device__ __nv_bfloat16 g_wqkv_hi[(size_t)QKVN * HIDN];
__device__ __nv_bfloat16 g_wqkv_lo[(size_t)QKVN * HIDN];
__device__ __nv_bfloat16 g_wout_hi[(size_t)HIDN * HIDN];
__device__ __nv_bfloat16 g_wout_lo[(size_t)HIDN * HIDN];
__device__ __nv_bfloat16 g_ctx_hi[(size_t)MROWS * HIDN];
__device__ __nv_bfloat16 g_ctx_lo[(size_t)MROWS * HIDN];

__device__ __nv_bfloat16 g_q_hi[(size_t)BSZ * NHEAD * SEQ * HDIM];
__device__ __nv_bfloat16 g_q_lo[(size_t)BSZ * NHEAD * SEQ * HDIM];
__device__ __nv_bfloat16 g_k_hi[(size_t)BSZ * NKVH * SEQ * HDIM];
__device__ __nv_bfloat16 g_k_lo[(size_t)BSZ * NKVH * SEQ * HDIM];
// V pre-transposed: [b][hk][d][SEQ]
__device__ __nv_bfloat16 g_vt_hi[(size_t)BSZ * NKVH * HDIM * SEQ];
__device__ __nv_bfloat16 g_vt_lo[(size_t)BSZ * NKVH * HDIM * SEQ];

// ---------------------------------------------------------------------------
// Portable tensor-core primitives (baseline PTX, valid on plain sm_103)
// ---------------------------------------------------------------------------
__device__ __forceinline__ uint32_t smem_u32(const void* p) {
    uint32_t a;
    asm("{ .reg .u64 t; cvta.to.shared.u64 t, %1; cvt.u32.u64 %0, t; }"
        : "=r"(a) : "l"(p));
    return a;
}

#define LDSM_X4(r0, r1, r2, r3, addr)                                          \
    asm volatile(                                                              \
        "ldmatrix.sync.aligned.m8n8.x4.shared.b16 {%0,%1,%2,%3}, [%4];"        \
        : "=r"(r0), "=r"(r1), "=r"(r2), "=r"(r3) : "r"(addr))

#define MMA16816(c, a, b)                                                      \
    asm volatile(                                                              \
        "mma.sync.aligned.m16n8k16.row.col.f32.bf16.bf16.f32 "                 \
        "{%0,%1,%2,%3}, {%4,%5,%6,%7}, {%8,%9}, {%0,%1,%2,%3};"                \
        : "+f"((c)[0]), "+f"((c)[1]), "+f"((c)[2]), "+f"((c)[3])               \
        : "r"((a)[0]), "r"((a)[1]), "r"((a)[2]), "r"((a)[3]),                  \
          "r"((b)[0]), "r"((b)[1]))

#define CP_ASYNC16(dst, src)                                                   \
    asm volatile("cp.async.cg.shared.global [%0], [%1], 16;"                   \
                 :: "r"(dst), "l"(src) : "memory")
#define CP_COMMIT() asm volatile("cp.async.commit_group;" ::: "memory")
#define CP_WAIT(n) asm volatile("cp.async.wait_group %0;" :: "n"(n) : "memory")

__device__ __forceinline__ void split2(float x, float y, uint32_t& hi,
                                       uint32_t& lo) {
    __nv_bfloat16 hx = __float2bfloat16(x), hy = __float2bfloat16(y);
    __nv_bfloat16 lx = __float2bfloat16(x - __bfloat162float(hx));
    __nv_bfloat16 ly = __float2bfloat16(y - __bfloat162float(hy));
    __nv_bfloat162 h2 = __halves2bfloat162(hx, hy);
    __nv_bfloat162 l2 = __halves2bfloat162(lx, ly);
    hi = *(uint32_t*)&h2;
    lo = *(uint32_t*)&l2;
}

// ---------------------------------------------------------------------------
// fp32 -> (bf16 hi, bf16 lo) split, 4 elems/thread
// ---------------------------------------------------------------------------
__global__ void split_kernel(const float4* __restrict__ src,
                             __nv_bfloat162* __restrict__ hi,
                             __nv_bfloat162* __restrict__ lo, int n4) {
    int i = blockIdx.x * blockDim.x + threadIdx.x;
    if (i >= n4) return;
    float4 x = src[i];
    uint32_t h0, l0, h1, l1;
    split2(x.x, x.y, h0, l0);
    split2(x.z, x.w, h1, l1);
    ((uint32_t*)hi)[2 * i] = h0;
    ((uint32_t*)hi)[2 * i + 1] = h1;
    ((uint32_t*)lo)[2 * i] = l0;
    ((uint32_t*)lo)[2 * i + 1] = l1;
}

// ---------------------------------------------------------------------------
// bf16x3 HMMA GEMM v4 (frozen — at sustainable mma.sync rate)
// ---------------------------------------------------------------------------
#define SROW2 80
#define TILE2 (128 * SROW2)
#define STAGE2 (4 * TILE2)
#define GEMM2_SMEM (2 * STAGE2)

template <int N, int K>
__global__ __launch_bounds__(128) void gemm_hmma4(
    const __nv_bfloat16* __restrict__ a_hi, const __nv_bfloat16* __restrict__ a_lo,
    const __nv_bfloat16* __restrict__ w_hi, const __nv_bfloat16* __restrict__ w_lo,
    float* __restrict__ C) {
    constexpr int NCH = K / 32;

    extern __shared__ __align__(16) char sm2[];
    const uint32_t sb = smem_u32(sm2);

    const int tid = threadIdx.x;
    const int lane = tid & 31;
    const int warp = tid >> 5;
    const int wm = warp >> 1;
    const int wn = warp & 1;
    const int m0 = blockIdx.y * 128;
    const int n0 = blockIdx.x * 128;

    auto stage_load = [&](int buf, int kk) {
        const uint32_t dst = sb + buf * STAGE2;
#pragma unroll
        for (int i = 0; i < 4; i++) {
            int lin = tid + i * 128;
            int row = lin >> 2;
            int c16 = lin & 3;
            uint32_t so = (uint32_t)row * SROW2 + c16 * 16;
            size_t ga = (size_t)(m0 + row) * K + kk + c16 * 8;
            size_t gw = (size_t)(n0 + row) * K + kk + c16 * 8;
            CP_ASYNC16(dst + 0 * TILE2 + so, a_hi + ga);
            CP_ASYNC16(dst + 1 * TILE2 + so, a_lo + ga);
            CP_ASYNC16(dst + 2 * TILE2 + so, w_hi + gw);
            CP_ASYNC16(dst + 3 * TILE2 + so, w_lo + gw);
        }
    };

    float acc[4][8][4];
#pragma unroll
    for (int t = 0; t < 4; t++)
#pragma unroll
        for (int n = 0; n < 8; n++)
#pragma unroll
            for (int j = 0; j < 4; j++) acc[t][n][j] = 0.0f;

    const uint32_t a_row = (uint32_t)(wm * 64 + ((lane >> 3) & 1) * 8 + (lane & 7));
    const uint32_t a_cb = (uint32_t)((lane >> 4) & 1) * 16;
    const uint32_t b_row = (uint32_t)(wn * 64 + ((lane >> 4) & 1) * 8 + (lane & 7));
    const uint32_t b_cb = (uint32_t)((lane >> 3) & 1) * 16;

    stage_load(0, 0);
    CP_COMMIT();

#pragma unroll 1
    for (int c = 0; c < NCH; c++) {
        if (c + 1 < NCH) {
            stage_load((c + 1) & 1, (c + 1) * 32);
            CP_COMMIT();
            CP_WAIT(1);
        } else {
            CP_WAIT(0);
        }
        __syncthreads();

        const uint32_t st = sb + (c & 1) * STAGE2;
        const uint32_t sAhi = st, sAlo = st + TILE2;
        const uint32_t sWhi = st + 2 * TILE2, sWlo = st + 3 * TILE2;

#pragma unroll
        for (int k16 = 0; k16 < 2; k16++) {
            const uint32_t kb = (uint32_t)k16 * 32;
            uint32_t ah[4][4], al[4][4];
#pragma unroll
            for (int t = 0; t < 4; t++) {
                LDSM_X4(ah[t][0], ah[t][1], ah[t][2], ah[t][3],
                        sAhi + (a_row + t * 16) * SROW2 + kb + a_cb);
                LDSM_X4(al[t][0], al[t][1], al[t][2], al[t][3],
                        sAlo + (a_row + t * 16) * SROW2 + kb + a_cb);
            }
            uint32_t bh[8][2], bl[8][2];
#pragma unroll
            for (int p = 0; p < 4; p++) {
                uint32_t r0, r1, r2, r3;
                LDSM_X4(r0, r1, r2, r3,
                        sWhi + (b_row + p * 16) * SROW2 + kb + b_cb);
                bh[2 * p][0] = r0; bh[2 * p][1] = r1;
                bh[2 * p + 1][0] = r2; bh[2 * p + 1][1] = r3;
                LDSM_X4(r0, r1, r2, r3,
                        sWlo + (b_row + p * 16) * SROW2 + kb + b_cb);
                bl[2 * p][0] = r0; bl[2 * p][1] = r1;
                bl[2 * p + 1][0] = r2; bl[2 * p + 1][1] = r3;
            }
#pragma unroll
            for (int t = 0; t < 4; t++)
#pragma unroll
                for (int n = 0; n < 8; n++) MMA16816(acc[t][n], ah[t], bh[n]);
#pragma unroll
            for (int t = 0; t < 4; t++)
#pragma unroll
                for (int n = 0; n < 8; n++) MMA16816(acc[t][n], al[t], bh[n]);
#pragma unroll
            for (int t = 0; t < 4; t++)
#pragma unroll
                for (int n = 0; n < 8; n++) MMA16816(acc[t][n], ah[t], bl[n]);
        }
        __syncthreads();
    }

#pragma unroll
    for (int t = 0; t < 4; t++) {
        int r0 = m0 + wm * 64 + t * 16 + (lane >> 2);
#pragma unroll
        for (int n = 0; n < 8; n++) {
            int col = n0 + wn * 64 + n * 8 + (lane & 3) * 2;
            *(float2*)&C[(size_t)r0 * N + col] = make_float2(acc[t][n][0], acc[t][n][1]);
            *(float2*)&C[(size_t)(r0 + 8) * N + col] = make_float2(acc[t][n][2], acc[t][n][3]);
        }
    }
}

// ---------------------------------------------------------------------------
// Position read: robust to int32 vs int64 storage of position_ids (arange).
// ---------------------------------------------------------------------------
__device__ __forceinline__ int read_pos(const int* __restrict__ pos32, int n) {
    bool is64 = (pos32[1] == 0);
    return pos32[is64 ? 2 * n : n];
}

// RoPE + scatter + bf16 hi/lo split
__global__ void rope_q_kernel(const int* __restrict__ pos32) {
    int idx = blockIdx.x * blockDim.x + threadIdx.x;
    int d = idx & 63;
    int h = (idx >> 6) & (NHEAD - 1);
    int s = (idx >> 10) & (SEQ - 1);
    int b = idx >> 21;

    int p = read_pos(pos32, b * SEQ + s);
    float invf = (float)exp(-((double)d / 64.0) * 9.210340371976184);
    float ang = (float)p * invf;
    float sn, c;
    sincosf(ang, &sn, &c);

    const float* src = g_qkv + ((size_t)b * SEQ + s) * QKVN + h * HDIM;
    float x1 = src[d], x2 = src[d + 64];
    float y1 = x1 * c - x2 * sn;
    float y2 = x2 * c + x1 * sn;

    size_t o = (((size_t)(b * NHEAD + h)) * SEQ + s) * HDIM;
    __nv_bfloat16 h1 = __float2bfloat16(y1);
    __nv_bfloat16 h2 = __float2bfloat16(y2);
    g_q_hi[o + d] = h1;
    g_q_hi[o + d + 64] = h2;
    g_q_lo[o + d] = __float2bfloat16(y1 - __bfloat162float(h1));
    g_q_lo[o + d + 64] = __float2bfloat16(y2 - __bfloat162float(h2));
}

__global__ void rope_k_kernel(const int* __restrict__ pos32) {
    int idx = blockIdx.x * blockDim.x + threadIdx.x;
    int d = idx & 63;
    int h = (idx >> 6) & (NKVH - 1);
    int s = (idx >> 8) & (SEQ - 1);
    int b = idx >> 19;

    int p = read_pos(pos32, b * SEQ + s);
    float invf = (float)exp(-((double)d / 64.0) * 9.210340371976184);
    float ang = (float)p * invf;
    float sn, c;
    sincosf(ang, &sn, &c);

    const float* src = g_qkv + ((size_t)b * SEQ + s) * QKVN + HIDN + h * HDIM;
    float x1 = src[d], x2 = src[d + 64];
    float y1 = x1 * c - x2 * sn;
    float y2 = x2 * c + x1 * sn;

    size_t o = (((size_t)(b * NKVH + h)) * SEQ + s) * HDIM;
    __nv_bfloat16 h1 = __float2bfloat16(y1);
    __nv_bfloat16 h2 = __float2bfloat16(y2);
    g_k_hi[o + d] = h1;
    g_k_hi[o + d + 64] = h2;
    g_k_lo[o + d] = __float2bfloat16(y1 - __bfloat162float(h1));
    g_k_lo[o + d + 64] = __float2bfloat16(y2 - __bfloat162float(h2));
}

// ---------------------------------------------------------------------------
// V split + transpose to [b][hk][d][SEQ].
// ---------------------------------------------------------------------------
__global__ void vt_split_kernel() {
    __shared__ __nv_bfloat16 thi[32][72];
    __shared__ __nv_bfloat16 tlo[32][72];
    const int s0 = blockIdx.x * 64;
    const int hk = blockIdx.y >> 2;
    const int d0 = (blockIdx.y & 3) * 32;
    const int b = blockIdx.z;
    const int t = threadIdx.x;

#pragma unroll
    for (int i = 0; i < 8; i++) {
        int s = (t >> 5) + i * 8;
        int d = t & 31;
        float x = g_qkv[((size_t)b * SEQ + s0 + s) * QKVN + HIDN + NKVH * HDIM +
                        hk * HDIM + d0 + d];
        __nv_bfloat16 h = __float2bfloat16(x);
        thi[d][s] = h;
        tlo[d][s] = __float2bfloat16(x - __bfloat162float(h));
    }
    __syncthreads();

    int d = t >> 3, c8 = (t & 7) * 8;
    size_t o = (((size_t)(b * NKVH + hk)) * HDIM + d0 + d) * SEQ + s0 + c8;
    *(uint4*)(g_vt_hi + o) = *(uint4*)&thi[d][c8];
    *(uint4*)(g_vt_lo + o) = *(uint4*)&tlo[d][c8];
}

// ---------------------------------------------------------------------------
// Flash attention via HMMA bf16x3, BQ=64 (R12 base) + K/V software pipeline:
// K ping-pongs between the (dead after prologue) Q smem region and the K
// region; K(kt+1) loads hide behind softmax+PV, V(kt+1) behind next S-MMA.
// ---------------------------------------------------------------------------
#define QS_STR 272
#define VT_STR 144
#define ATTN_SMEM (4 * 64 * QS_STR + 2 * 128 * VT_STR) /* 106496 */

__global__ __launch_bounds__(128, 2) void attn_hmma() {
    extern __shared__ __align__(16) char smr[];
    const uint32_t sbase = smem_u32(smr);
    // region A (Q, then K stage 1), region B (K stage 0), V
    const uint32_t sQhi = sbase;
    const uint32_t sQlo = sQhi + 64 * QS_STR;
    const uint32_t sKhi = sQlo + 64 * QS_STR;
    const uint32_t sKlo = sKhi + 64 * QS_STR;
    const uint32_t sVhi = sKlo + 64 * QS_STR;
    const uint32_t sVlo = sVhi + 128 * VT_STR;

    const int tid = threadIdx.x;
    const int lane = tid & 31;
    const int wm = tid >> 5;
    const int qb = gridDim.x - 1 - blockIdx.x; // heaviest first
    const int h = blockIdx.y;
    const int b = blockIdx.z;
    const int q0 = qb * 64;
    const int hk = h / NREP;

    const __nv_bfloat16* Qhig = g_q_hi + (((size_t)(b * NHEAD + h)) * SEQ + q0) * HDIM;
    const __nv_bfloat16* Qlog = g_q_lo + (((size_t)(b * NHEAD + h)) * SEQ + q0) * HDIM;
    const __nv_bfloat16* Khig = g_k_hi + ((size_t)(b * NKVH + hk)) * SEQ * HDIM;
    const __nv_bfloat16* Klog = g_k_lo + ((size_t)(b * NKVH + hk)) * SEQ * HDIM;
    const __nv_bfloat16* Vthig = g_vt_hi + ((size_t)(b * NKVH + hk)) * HDIM * SEQ;
    const __nv_bfloat16* Vtlog = g_vt_lo + ((size_t)(b * NKVH + hk)) * HDIM * SEQ;

    auto load_k = [&](uint32_t dhi, uint32_t dlo, int k0) {
#pragma unroll
        for (int i = 0; i < 8; i++) {
            int lin = tid + i * 128;
            int row = lin >> 4, c = lin & 15;
            uint32_t so = (uint32_t)row * QS_STR + c * 16;
            size_t go = (size_t)(k0 + row) * HDIM + c * 8;
            CP_ASYNC16(dhi + so, Khig + go);
            CP_ASYNC16(dlo + so, Klog + go);
        }
    };
    auto load_v = [&](int k0) {
#pragma unroll
        for (int i = 0; i < 8; i++) {
            int lin = tid + i * 128;
            int row = lin >> 3, c = lin & 7;
            uint32_t so = (uint32_t)row * VT_STR + c * 16;
            size_t go = (size_t)row * SEQ + k0 + c * 8;
            CP_ASYNC16(sVhi + so, Vthig + go);
            CP_ASYNC16(sVlo + so, Vtlog + go);
        }
    };

    // prologue: group0 = Q tiles, group1 = K0 + V0
#pragma unroll
    for (int i = 0; i < 8; i++) {
        int lin = tid + i * 128;
        int row = lin >> 4, c = lin & 15;
        uint32_t so = (uint32_t)row * QS_STR + c * 16;
        size_t go = (size_t)row * HDIM + c * 8;
        CP_ASYNC16(sQhi + so, Qhig + go);
        CP_ASYNC16(sQlo + so, Qlog + go);
    }
    CP_COMMIT();
    load_k(sKhi, sKlo, 0);
    load_v(0);
    CP_COMMIT();

    CP_WAIT(1); // Q visible (group0 done)
    __syncthreads();

    const uint32_t a_row = (uint32_t)(wm * 16 + ((lane >> 3) & 1) * 8 + (lane & 7));
    const uint32_t a_cb = (uint32_t)((lane >> 4) & 1) * 16;
    const uint32_t b_row = (uint32_t)(((lane >> 4) & 1) * 8 + (lane & 7));
    const uint32_t b_cb = (uint32_t)((lane >> 3) & 1) * 16;

    uint32_t qhi[8][4], qlo[8][4];
#pragma unroll
    for (int k16 = 0; k16 < 8; k16++) {
        LDSM_X4(qhi[k16][0], qhi[k16][1], qhi[k16][2], qhi[k16][3],
                sQhi + a_row * QS_STR + k16 * 32 + a_cb);
        LDSM_X4(qlo[k16][0], qlo[k16][1], qlo[k16][2], qlo[k16][3],
                sQlo + a_row * QS_STR + k16 * 32 + a_cb);
    }
    __syncthreads(); // all warps done reading Q region; it becomes K stage 1

    float o[16][4];
#pragma unroll
    for (int n = 0; n < 16; n++)
#pragma unroll
        for (int j = 0; j < 4; j++) o[n][j] = 0.0f;
    float m0r = -FLT_MAX, m1r = -FLT_MAX, l0 = 0.0f, l1 = 0.0f;

    const float scale = 0.08838834764831845f;
    const int rowg0 = q0 + wm * 16 + (lane >> 2);
    const int rowg1 = rowg0 + 8;

#pragma unroll 1
    for (int kt = 0; kt <= qb; kt++) {
        // K(kt) ready; V(kt) may still be in flight (kt>=1)
        if (kt == 0) { CP_WAIT(0); } else { CP_WAIT(1); }
        __syncthreads();

        const uint32_t kcur_hi = (kt & 1) ? sQhi : sKhi;
        const uint32_t kcur_lo = (kt & 1) ? sQlo : sKlo;

        // ---- S = Q K^T (bf16x3, product-major) ----
        float s[8][4];
#pragma unroll
        for (int n = 0; n < 8; n++)
#pragma unroll
            for (int j = 0; j < 4; j++) s[n][j] = 0.0f;

#pragma unroll
        for (int k16 = 0; k16 < 8; k16++) {
            uint32_t bh[8][2], bl[8][2];
#pragma unroll
            for (int p = 0; p < 4; p++) {
                uint32_t r0, r1, r2, r3;
                LDSM_X4(r0, r1, r2, r3,
                        kcur_hi + (p * 16 + b_row) * QS_STR + k16 * 32 + b_cb);
                bh[2 * p][0] = r0; bh[2 * p][1] = r1;
                bh[2 * p + 1][0] = r2; bh[2 * p + 1][1] = r3;
                LDSM_X4(r0, r1, r2, r3,
                        kcur_lo + (p * 16 + b_row) * QS_STR + k16 * 32 + b_cb);
                bl[2 * p][0] = r0; bl[2 * p][1] = r1;
                bl[2 * p + 1][0] = r2; bl[2 * p + 1][1] = r3;
            }
#pragma unroll
            for (int n = 0; n < 8; n++) MMA16816(s[n], qhi[k16], bh[n]);
#pragma unroll
            for (int n = 0; n < 8; n++) MMA16816(s[n], qlo[k16], bh[n]);
#pragma unroll
            for (int n = 0; n < 8; n++) MMA16816(s[n], qhi[k16], bl[n]);
        }

        // prefetch K(kt+1) into alternate stage (hides behind softmax+PV)
        if (kt < qb) {
            load_k((kt & 1) ? sKhi : sQhi, (kt & 1) ? sKlo : sQlo, (kt + 1) * 64);
            CP_COMMIT();
        }

        // ---- scale + causal mask ----
#pragma unroll
        for (int n = 0; n < 8; n++)
#pragma unroll
            for (int j = 0; j < 4; j++) s[n][j] *= scale;
        if (kt == qb) {
            const int colb = kt * 64 + (lane & 3) * 2;
#pragma unroll
            for (int n = 0; n < 8; n++) {
#pragma unroll
                for (int e = 0; e < 2; e++) {
                    int col = colb + n * 8 + e;
                    if (col > rowg0) s[n][e] = -1e30f;
                    if (col > rowg1) s[n][2 + e] = -1e30f;
                }
            }
        }

        // ---- online softmax (registers + quad shfl) ----
        float mx0 = -FLT_MAX, mx1 = -FLT_MAX;
#pragma unroll
        for (int n = 0; n < 8; n++) {
            mx0 = fmaxf(mx0, fmaxf(s[n][0], s[n][1]));
            mx1 = fmaxf(mx1, fmaxf(s[n][2], s[n][3]));
        }
        mx0 = fmaxf(mx0, __shfl_xor_sync(0xffffffffu, mx0, 1));
        mx0 = fmaxf(mx0, __shfl_xor_sync(0xffffffffu, mx0, 2));
        mx1 = fmaxf(mx1, __shfl_xor_sync(0xffffffffu, mx1, 1));
        mx1 = fmaxf(mx1, __shfl_xor_sync(0xffffffffu, mx1, 2));
        float mn0 = fmaxf(m0r, mx0), mn1 = fmaxf(m1r, mx1);
        float corr0 = __expf(m0r - mn0), corr1 = __expf(m1r - mn1);
        m0r = mn0; m1r = mn1;

        float rs0 = 0.0f, rs1 = 0.0f;
#pragma unroll
        for (int n = 0; n < 8; n++) {
            s[n][0] = __expf(s[n][0] - mn0);
            s[n][1] = __expf(s[n][1] - mn0);
            s[n][2] = __expf(s[n][2] - mn1);
            s[n][3] = __expf(s[n][3] - mn1);
            rs0 += s[n][0] + s[n][1];
            rs1 += s[n][2] + s[n][3];
        }
        rs0 += __shfl_xor_sync(0xffffffffu, rs0, 1);
        rs0 += __shfl_xor_sync(0xffffffffu, rs0, 2);
        rs1 += __shfl_xor_sync(0xffffffffu, rs1, 1);
        rs1 += __shfl_xor_sync(0xffffffffu, rs1, 2);
        l0 = l0 * corr0 + rs0;
        l1 = l1 * corr1 + rs1;

#pragma unroll
        for (int n = 0; n < 16; n++) {
            o[n][0] *= corr0; o[n][1] *= corr0;
            o[n][2] *= corr1; o[n][3] *= corr1;
        }

        // V(kt) ready (older group); K(kt+1) may still be in flight
        if (kt < qb) { CP_WAIT(1); } else { CP_WAIT(0); }
        __syncthreads();

        // ---- O += P V (bf16x3), P frags straight from S regs ----
#pragma unroll
        for (int j = 0; j < 4; j++) {
            uint32_t ah[4], al[4];
            split2(s[2 * j][0], s[2 * j][1], ah[0], al[0]);
            split2(s[2 * j][2], s[2 * j][3], ah[1], al[1]);
            split2(s[2 * j + 1][0], s[2 * j + 1][1], ah[2], al[2]);
            split2(s[2 * j + 1][2], s[2 * j + 1][3], ah[3], al[3]);
#pragma unroll
            for (int p = 0; p < 8; p++) {
                uint32_t r0, r1, r2, r3, u0, u1, u2, u3;
                LDSM_X4(r0, r1, r2, r3,
                        sVhi + (p * 16 + b_row) * VT_STR + j * 32 + b_cb);
                LDSM_X4(u0, u1, u2, u3,
                        sVlo + (p * 16 + b_row) * VT_STR + j * 32 + b_cb);
                uint32_t bh0[2] = {r0, r1}, bh1[2] = {r2, r3};
                uint32_t bl0[2] = {u0, u1}, bl1[2] = {u2, u3};
                MMA16816(o[2 * p], ah, bh0);
                MMA16816(o[2 * p + 1], ah, bh1);
                MMA16816(o[2 * p], al, bh0);
                MMA16816(o[2 * p + 1], al, bh1);
                MMA16816(o[2 * p], ah, bl0);
                MMA16816(o[2 * p + 1], ah, bl1);
            }
        }

        __syncthreads(); // all warps done reading V before overwrite
        if (kt < qb) {
            load_v((kt + 1) * 64); // hides behind next iteration's S-MMA
            CP_COMMIT();
        }
    }

    // ---- epilogue: normalize, split hi/lo, write [b, s, h, d] ----
    float linv0 = 1.0f / l0, linv1 = 1.0f / l1;
    size_t base0 = (((size_t)b * SEQ + rowg0) * NHEAD + h) * HDIM + (lane & 3) * 2;
    size_t base1 = (((size_t)b * SEQ + rowg1) * NHEAD + h) * HDIM + (lane & 3) * 2;
#pragma unroll
    for (int n = 0; n < 16; n++) {
        uint32_t hi, lo;
        split2(o[n][0] * linv0, o[n][1] * linv0, hi, lo);
        *(uint32_t*)(g_ctx_hi + base0 + n * 8) = hi;
        *(uint32_t*)(g_ctx_lo + base0 + n * 8) = lo;
        split2(o[n][2] * linv1, o[n][3] * linv1, hi, lo);
        *(uint32_t*)(g_ctx_hi + base1 + n * 8) = hi;
        *(uint32_t*)(g_ctx_lo + base1 + n * 8) = lo;
    }
}

// ---------------------------------------------------------------------------
extern "C" void kernel_launch(void* const* d_in, const int* in_sizes, int n_in,
                              void* d_out, int out_size) {
    const float* hs = (const float*)d_in[0];
    const float* w_qkv = (const float*)d_in[1];
    const float* w_out = (const float*)d_in[2];
    const int* pos32 = (const int*)d_in[4];
    float* out = (float*)d_out;

    float* qkv;
    __nv_bfloat16 *hs_hi, *hs_lo, *wq_hi, *wq_lo, *wo_hi, *wo_lo, *cx_hi, *cx_lo;
    cudaGetSymbolAddress((void**)&qkv, g_qkv);
    cudaGetSymbolAddress((void**)&hs_hi, g_hs_hi);
    cudaGetSymbolAddress((void**)&hs_lo, g_hs_lo);
    cudaGetSymbolAddress((void**)&wq_hi, g_wqkv_hi);
    cudaGetSymbolAddress((void**)&wq_lo, g_wqkv_lo);
    cudaGetSymbolAddress((void**)&wo_hi, g_wout_hi);
    cudaGetSymbolAddress((void**)&wo_lo, g_wout_lo);
    cudaGetSymbolAddress((void**)&cx_hi, g_ctx_hi);
    cudaGetSymbolAddress((void**)&cx_lo, g_ctx_lo);

    cudaFuncSetAttribute(gemm_hmma4<QKVN, HIDN>,
                         cudaFuncAttributeMaxDynamicSharedMemorySize, GEMM2_SMEM);
    cudaFuncSetAttribute(gemm_hmma4<HIDN, HIDN>,
                         cudaFuncAttributeMaxDynamicSharedMemorySize, GEMM2_SMEM);
    cudaFuncSetAttribute(attn_hmma, cudaFuncAttributeMaxDynamicSharedMemorySize,
                         ATTN_SMEM);

    // 0. bf16 hi/lo splits of inputs
    {
        int n4;
        n4 = (MROWS * HIDN) / 4;
        split_kernel<<<(n4 + 255) / 256, 256>>>((const float4*)hs,
                                                (__nv_bfloat162*)hs_hi,
                                                (__nv_bfloat162*)hs_lo, n4);
        n4 = (QKVN * HIDN) / 4;
        split_kernel<<<(n4 + 255) / 256, 256>>>((const float4*)w_qkv,
                                                (__nv_bfloat162*)wq_hi,
                                                (__nv_bfloat162*)wq_lo, n4);
        n4 = (HIDN * HIDN) / 4;
        split_kernel<<<(n4 + 255) / 256, 256>>>((const float4*)w_out,
                                                (__nv_bfloat162*)wo_hi,
                                                (__nv_bfloat162*)wo_lo, n4);
    }

    // 1. QKV GEMM (HMMA bf16x3)
    {
        dim3 grid(QKVN / 128, MROWS / 128);
        gemm_hmma4<QKVN, HIDN><<<grid, 128, GEMM2_SMEM>>>(hs_hi, hs_lo, wq_hi,
                                                          wq_lo, qkv);
    }

    // 2. RoPE + scatter; V split+transpose
    rope_q_kernel<<<(BSZ * SEQ * NHEAD * 64) / 256, 256>>>(pos32);
    rope_k_kernel<<<(BSZ * SEQ * NKVH * 64) / 256, 256>>>(pos32);
    {
        dim3 grid(SEQ / 64, (HDIM / 32) * NKVH, BSZ);
        vt_split_kernel<<<grid, 256>>>();
    }

    // 3. Flash attention (HMMA bf16x3, pipelined K/V)
    {
        dim3 grid(SEQ / 64, NHEAD, BSZ);
        attn_hmma<<<grid, 128, ATTN_SMEM>>>();
    }

    // 4. Output GEMM (HMMA bf16x3)
    {
        dim3 grid(HIDN / 128, MROWS / 128);
        gemm_hmma4<HIDN, HIDN><<<grid, 128, GEMM2_SMEM>>>(cx_hi, cx_lo, wo_hi,
                                                          wo_lo, out);
    }
}

// round 15
// speedup vs baseline: 1.0776x; 1.0452x over previous
#include <cuda_runtime.h>
#include <cuda_bf16.h>
#include <cuda_fp16.h>
#include <math.h>
#include <float.h>
#include <stdint.h>

#define BSZ 2
#define SEQ 2048
#define HIDN 2048
#define NHEAD 16
#define NKVH 4
#define HDIM 128
#define NREP (NHEAD / NKVH)
#define QKVN (HIDN + 2 * NKVH * HDIM) /* 3072 */
#define MROWS (BSZ * SEQ)             /* 4096 */

// ---------------------------------------------------------------------------
// Scratch (static device globals; no runtime allocation allowed)
// ---------------------------------------------------------------------------
__device__ float g_qkv[(size_t)MROWS * QKVN];

__device__ __nv_bfloat16 g_hs_hi[(size_t)MROWS * HIDN];
__device__ __nv_bfloat16 g_hs_lo[(size_t)MROWS * HIDN];
__device__ __nv_bfloat16 g_wqkv_hi[(size_t)QKVN * HIDN];
__device__ __nv_bfloat16 g_wqkv_lo[(size_t)QKVN * HIDN];
__device__ __nv_bfloat16 g_wout_hi[(size_t)HIDN * HIDN];
__device__ __nv_bfloat16 g_wout_lo[(size_t)HIDN * HIDN];
__device__ __nv_bfloat16 g_ctx_hi[(size_t)MROWS * HIDN];
__device__ __nv_bfloat16 g_ctx_lo[(size_t)MROWS * HIDN];

__device__ __nv_bfloat16 g_q_hi[(size_t)BSZ * NHEAD * SEQ * HDIM];
__device__ __nv_bfloat16 g_q_lo[(size_t)BSZ * NHEAD * SEQ * HDIM];
__device__ __nv_bfloat16 g_k_hi[(size_t)BSZ * NKVH * SEQ * HDIM];
__device__ __nv_bfloat16 g_k_lo[(size_t)BSZ * NKVH * SEQ * HDIM];
// V pre-transposed, single fp16: [b][hk][d][SEQ]
__device__ __half g_vt_h[(size_t)BSZ * NKVH * HDIM * SEQ];

// ---------------------------------------------------------------------------
// Portable tensor-core primitives (baseline PTX, valid on plain sm_103)
// ---------------------------------------------------------------------------
__device__ __forceinline__ uint32_t smem_u32(const void* p) {
    uint32_t a;
    asm("{ .reg .u64 t; cvta.to.shared.u64 t, %1; cvt.u32.u64 %0, t; }"
        : "=r"(a) : "l"(p));
    return a;
}

#define LDSM_X4(r0, r1, r2, r3, addr)                                          \
    asm volatile(                                                              \
        "ldmatrix.sync.aligned.m8n8.x4.shared.b16 {%0,%1,%2,%3}, [%4];"        \
        : "=r"(r0), "=r"(r1), "=r"(r2), "=r"(r3) : "r"(addr))

#define MMA16816(c, a, b)                                                      \
    asm volatile(                                                              \
        "mma.sync.aligned.m16n8k16.row.col.f32.bf16.bf16.f32 "                 \
        "{%0,%1,%2,%3}, {%4,%5,%6,%7}, {%8,%9}, {%0,%1,%2,%3};"                \
        : "+f"((c)[0]), "+f"((c)[1]), "+f"((c)[2]), "+f"((c)[3])               \
        : "r"((a)[0]), "r"((a)[1]), "r"((a)[2]), "r"((a)[3]),                  \
          "r"((b)[0]), "r"((b)[1]))

#define MMAF16(c, a, b)                                                        \
    asm volatile(                                                              \
        "mma.sync.aligned.m16n8k16.row.col.f32.f16.f16.f32 "                   \
        "{%0,%1,%2,%3}, {%4,%5,%6,%7}, {%8,%9}, {%0,%1,%2,%3};"                \
        : "+f"((c)[0]), "+f"((c)[1]), "+f"((c)[2]), "+f"((c)[3])               \
        : "r"((a)[0]), "r"((a)[1]), "r"((a)[2]), "r"((a)[3]),                  \
          "r"((b)[0]), "r"((b)[1]))

#define CP_ASYNC16(dst, src)                                                   \
    asm volatile("cp.async.cg.shared.global [%0], [%1], 16;"                   \
                 :: "r"(dst), "l"(src) : "memory")
#define CP_COMMIT() asm volatile("cp.async.commit_group;" ::: "memory")
#define CP_WAIT(n) asm volatile("cp.async.wait_group %0;" :: "n"(n) : "memory")

__device__ __forceinline__ void split2(float x, float y, uint32_t& hi,
                                       uint32_t& lo) {
    __nv_bfloat16 hx = __float2bfloat16(x), hy = __float2bfloat16(y);
    __nv_bfloat16 lx = __float2bfloat16(x - __bfloat162float(hx));
    __nv_bfloat16 ly = __float2bfloat16(y - __bfloat162float(hy));
    __nv_bfloat162 h2 = __halves2bfloat162(hx, hy);
    __nv_bfloat162 l2 = __halves2bfloat162(lx, ly);
    hi = *(uint32_t*)&h2;
    lo = *(uint32_t*)&l2;
}

// fp16 hi/lo split of a float pair (for P fragments)
__device__ __forceinline__ void split2h(float x, float y, uint32_t& hi,
                                        uint32_t& lo) {
    __half hx = __float2half_rn(x), hy = __float2half_rn(y);
    __half lx = __float2half_rn(x - __half2float(hx));
    __half ly = __float2half_rn(y - __half2float(hy));
    __half2 h2 = __halves2half2(hx, hy);
    __half2 l2 = __halves2half2(lx, ly);
    hi = *(uint32_t*)&h2;
    lo = *(uint32_t*)&l2;
}

// ---------------------------------------------------------------------------
// fp32 -> (bf16 hi, bf16 lo) split, 4 elems/thread
// ---------------------------------------------------------------------------
__global__ void split_kernel(const float4* __restrict__ src,
                             __nv_bfloat162* __restrict__ hi,
                             __nv_bfloat162* __restrict__ lo, int n4) {
    int i = blockIdx.x * blockDim.x + threadIdx.x;
    if (i >= n4) return;
    float4 x = src[i];
    uint32_t h0, l0, h1, l1;
    split2(x.x, x.y, h0, l0);
    split2(x.z, x.w, h1, l1);
    ((uint32_t*)hi)[2 * i] = h0;
    ((uint32_t*)hi)[2 * i + 1] = h1;
    ((uint32_t*)lo)[2 * i] = l0;
    ((uint32_t*)lo)[2 * i + 1] = l1;
}

// ---------------------------------------------------------------------------
// bf16x3 HMMA GEMM v4 (frozen — at sustainable mma.sync rate)
// ---------------------------------------------------------------------------
#define SROW2 80
#define TILE2 (128 * SROW2)
#define STAGE2 (4 * TILE2)
#define GEMM2_SMEM (2 * STAGE2)

template <int N, int K>
__global__ __launch_bounds__(128) void gemm_hmma4(
    const __nv_bfloat16* __restrict__ a_hi, const __nv_bfloat16* __restrict__ a_lo,
    const __nv_bfloat16* __restrict__ w_hi, const __nv_bfloat16* __restrict__ w_lo,
    float* __restrict__ C) {
    constexpr int NCH = K / 32;

    extern __shared__ __align__(16) char sm2[];
    const uint32_t sb = smem_u32(sm2);

    const int tid = threadIdx.x;
    const int lane = tid & 31;
    const int warp = tid >> 5;
    const int wm = warp >> 1;
    const int wn = warp & 1;
    const int m0 = blockIdx.y * 128;
    const int n0 = blockIdx.x * 128;

    auto stage_load = [&](int buf, int kk) {
        const uint32_t dst = sb + buf * STAGE2;
#pragma unroll
        for (int i = 0; i < 4; i++) {
            int lin = tid + i * 128;
            int row = lin >> 2;
            int c16 = lin & 3;
            uint32_t so = (uint32_t)row * SROW2 + c16 * 16;
            size_t ga = (size_t)(m0 + row) * K + kk + c16 * 8;
            size_t gw = (size_t)(n0 + row) * K + kk + c16 * 8;
            CP_ASYNC16(dst + 0 * TILE2 + so, a_hi + ga);
            CP_ASYNC16(dst + 1 * TILE2 + so, a_lo + ga);
            CP_ASYNC16(dst + 2 * TILE2 + so, w_hi + gw);
            CP_ASYNC16(dst + 3 * TILE2 + so, w_lo + gw);
        }
    };

    float acc[4][8][4];
#pragma unroll
    for (int t = 0; t < 4; t++)
#pragma unroll
        for (int n = 0; n < 8; n++)
#pragma unroll
            for (int j = 0; j < 4; j++) acc[t][n][j] = 0.0f;

    const uint32_t a_row = (uint32_t)(wm * 64 + ((lane >> 3) & 1) * 8 + (lane & 7));
    const uint32_t a_cb = (uint32_t)((lane >> 4) & 1) * 16;
    const uint32_t b_row = (uint32_t)(wn * 64 + ((lane >> 4) & 1) * 8 + (lane & 7));
    const uint32_t b_cb = (uint32_t)((lane >> 3) & 1) * 16;

    stage_load(0, 0);
    CP_COMMIT();

#pragma unroll 1
    for (int c = 0; c < NCH; c++) {
        if (c + 1 < NCH) {
            stage_load((c + 1) & 1, (c + 1) * 32);
            CP_COMMIT();
            CP_WAIT(1);
        } else {
            CP_WAIT(0);
        }
        __syncthreads();

        const uint32_t st = sb + (c & 1) * STAGE2;
        const uint32_t sAhi = st, sAlo = st + TILE2;
        const uint32_t sWhi = st + 2 * TILE2, sWlo = st + 3 * TILE2;

#pragma unroll
        for (int k16 = 0; k16 < 2; k16++) {
            const uint32_t kb = (uint32_t)k16 * 32;
            uint32_t ah[4][4], al[4][4];
#pragma unroll
            for (int t = 0; t < 4; t++) {
                LDSM_X4(ah[t][0], ah[t][1], ah[t][2], ah[t][3],
                        sAhi + (a_row + t * 16) * SROW2 + kb + a_cb);
                LDSM_X4(al[t][0], al[t][1], al[t][2], al[t][3],
                        sAlo + (a_row + t * 16) * SROW2 + kb + a_cb);
            }
            uint32_t bh[8][2], bl[8][2];
#pragma unroll
            for (int p = 0; p < 4; p++) {
                uint32_t r0, r1, r2, r3;
                LDSM_X4(r0, r1, r2, r3,
                        sWhi + (b_row + p * 16) * SROW2 + kb + b_cb);
                bh[2 * p][0] = r0; bh[2 * p][1] = r1;
                bh[2 * p + 1][0] = r2; bh[2 * p + 1][1] = r3;
                LDSM_X4(r0, r1, r2, r3,
                        sWlo + (b_row + p * 16) * SROW2 + kb + b_cb);
                bl[2 * p][0] = r0; bl[2 * p][1] = r1;
                bl[2 * p + 1][0] = r2; bl[2 * p + 1][1] = r3;
            }
#pragma unroll
            for (int t = 0; t < 4; t++)
#pragma unroll
                for (int n = 0; n < 8; n++) MMA16816(acc[t][n], ah[t], bh[n]);
#pragma unroll
            for (int t = 0; t < 4; t++)
#pragma unroll
                for (int n = 0; n < 8; n++) MMA16816(acc[t][n], al[t], bh[n]);
#pragma unroll
            for (int t = 0; t < 4; t++)
#pragma unroll
                for (int n = 0; n < 8; n++) MMA16816(acc[t][n], ah[t], bl[n]);
        }
        __syncthreads();
    }

#pragma unroll
    for (int t = 0; t < 4; t++) {
        int r0 = m0 + wm * 64 + t * 16 + (lane >> 2);
#pragma unroll
        for (int n = 0; n < 8; n++) {
            int col = n0 + wn * 64 + n * 8 + (lane & 3) * 2;
            *(float2*)&C[(size_t)r0 * N + col] = make_float2(acc[t][n][0], acc[t][n][1]);
            *(float2*)&C[(size_t)(r0 + 8) * N + col] = make_float2(acc[t][n][2], acc[t][n][3]);
        }
    }
}

// ---------------------------------------------------------------------------
// Position read: robust to int32 vs int64 storage of position_ids (arange).
// ---------------------------------------------------------------------------
__device__ __forceinline__ int read_pos(const int* __restrict__ pos32, int n) {
    bool is64 = (pos32[1] == 0);
    return pos32[is64 ? 2 * n : n];
}

// RoPE + scatter + bf16 hi/lo split
__global__ void rope_q_kernel(const int* __restrict__ pos32) {
    int idx = blockIdx.x * blockDim.x + threadIdx.x;
    int d = idx & 63;
    int h = (idx >> 6) & (NHEAD - 1);
    int s = (idx >> 10) & (SEQ - 1);
    int b = idx >> 21;

    int p = read_pos(pos32, b * SEQ + s);
    float invf = (float)exp(-((double)d / 64.0) * 9.210340371976184);
    float ang = (float)p * invf;
    float sn, c;
    sincosf(ang, &sn, &c);

    const float* src = g_qkv + ((size_t)b * SEQ + s) * QKVN + h * HDIM;
    float x1 = src[d], x2 = src[d + 64];
    float y1 = x1 * c - x2 * sn;
    float y2 = x2 * c + x1 * sn;

    size_t o = (((size_t)(b * NHEAD + h)) * SEQ + s) * HDIM;
    __nv_bfloat16 h1 = __float2bfloat16(y1);
    __nv_bfloat16 h2 = __float2bfloat16(y2);
    g_q_hi[o + d] = h1;
    g_q_hi[o + d + 64] = h2;
    g_q_lo[o + d] = __float2bfloat16(y1 - __bfloat162float(h1));
    g_q_lo[o + d + 64] = __float2bfloat16(y2 - __bfloat162float(h2));
}

__global__ void rope_k_kernel(const int* __restrict__ pos32) {
    int idx = blockIdx.x * blockDim.x + threadIdx.x;
    int d = idx & 63;
    int h = (idx >> 6) & (NKVH - 1);
    int s = (idx >> 8) & (SEQ - 1);
    int b = idx >> 19;

    int p = read_pos(pos32, b * SEQ + s);
    float invf = (float)exp(-((double)d / 64.0) * 9.210340371976184);
    float ang = (float)p * invf;
    float sn, c;
    sincosf(ang, &sn, &c);

    const float* src = g_qkv + ((size_t)b * SEQ + s) * QKVN + HIDN + h * HDIM;
    float x1 = src[d], x2 = src[d + 64];
    float y1 = x1 * c - x2 * sn;
    float y2 = x2 * c + x1 * sn;

    size_t o = (((size_t)(b * NKVH + h)) * SEQ + s) * HDIM;
    __nv_bfloat16 h1 = __float2bfloat16(y1);
    __nv_bfloat16 h2 = __float2bfloat16(y2);
    g_k_hi[o + d] = h1;
    g_k_hi[o + d + 64] = h2;
    g_k_lo[o + d] = __float2bfloat16(y1 - __bfloat162float(h1));
    g_k_lo[o + d + 64] = __float2bfloat16(y2 - __bfloat162float(h2));
}

// ---------------------------------------------------------------------------
// V fp16 + transpose to [b][hk][d][SEQ].
// ---------------------------------------------------------------------------
__global__ void vt_split_kernel() {
    __shared__ __half th[32][72];
    const int s0 = blockIdx.x * 64;
    const int hk = blockIdx.y >> 2;
    const int d0 = (blockIdx.y & 3) * 32;
    const int b = blockIdx.z;
    const int t = threadIdx.x;

#pragma unroll
    for (int i = 0; i < 8; i++) {
        int s = (t >> 5) + i * 8;
        int d = t & 31;
        float x = g_qkv[((size_t)b * SEQ + s0 + s) * QKVN + HIDN + NKVH * HDIM +
                        hk * HDIM + d0 + d];
        th[d][s] = __float2half_rn(x);
    }
    __syncthreads();

    int d = t >> 3, c8 = (t & 7) * 8;
    size_t o = (((size_t)(b * NKVH + hk)) * HDIM + d0 + d) * SEQ + s0 + c8;
    *(uint4*)(g_vt_h + o) = *(uint4*)&th[d][c8];
}

// ---------------------------------------------------------------------------
// Flash attention: QK^T bf16x3 + PV fp16x2 (P hi/lo fp16, V single fp16).
// BQ=64, pipelined K/V loads (R14 structure).
// ---------------------------------------------------------------------------
#define QS_STR 272
#define VT_STR 144
#define ATTN_SMEM (4 * 64 * QS_STR + 128 * VT_STR) /* 88064 */

__global__ __launch_bounds__(128, 2) void attn_hmma() {
    extern __shared__ __align__(16) char smr[];
    const uint32_t sbase = smem_u32(smr);
    // region A (Q, then K stage 1), region B (K stage 0), V (fp16 single)
    const uint32_t sQhi = sbase;
    const uint32_t sQlo = sQhi + 64 * QS_STR;
    const uint32_t sKhi = sQlo + 64 * QS_STR;
    const uint32_t sKlo = sKhi + 64 * QS_STR;
    const uint32_t sVh = sKlo + 64 * QS_STR;

    const int tid = threadIdx.x;
    const int lane = tid & 31;
    const int wm = tid >> 5;
    const int qb = gridDim.x - 1 - blockIdx.x; // heaviest first
    const int h = blockIdx.y;
    const int b = blockIdx.z;
    const int q0 = qb * 64;
    const int hk = h / NREP;

    const __nv_bfloat16* Qhig = g_q_hi + (((size_t)(b * NHEAD + h)) * SEQ + q0) * HDIM;
    const __nv_bfloat16* Qlog = g_q_lo + (((size_t)(b * NHEAD + h)) * SEQ + q0) * HDIM;
    const __nv_bfloat16* Khig = g_k_hi + ((size_t)(b * NKVH + hk)) * SEQ * HDIM;
    const __nv_bfloat16* Klog = g_k_lo + ((size_t)(b * NKVH + hk)) * SEQ * HDIM;
    const __half* Vthg = g_vt_h + ((size_t)(b * NKVH + hk)) * HDIM * SEQ;

    auto load_k = [&](uint32_t dhi, uint32_t dlo, int k0) {
#pragma unroll
        for (int i = 0; i < 8; i++) {
            int lin = tid + i * 128;
            int row = lin >> 4, c = lin & 15;
            uint32_t so = (uint32_t)row * QS_STR + c * 16;
            size_t go = (size_t)(k0 + row) * HDIM + c * 8;
            CP_ASYNC16(dhi + so, Khig + go);
            CP_ASYNC16(dlo + so, Klog + go);
        }
    };
    auto load_v = [&](int k0) {
#pragma unroll
        for (int i = 0; i < 8; i++) {
            int lin = tid + i * 128;
            int row = lin >> 3, c = lin & 7;
            uint32_t so = (uint32_t)row * VT_STR + c * 16;
            size_t go = (size_t)row * SEQ + k0 + c * 8;
            CP_ASYNC16(sVh + so, Vthg + go);
        }
    };

    // prologue: group0 = Q tiles, group1 = K0 + V0
#pragma unroll
    for (int i = 0; i < 8; i++) {
        int lin = tid + i * 128;
        int row = lin >> 4, c = lin & 15;
        uint32_t so = (uint32_t)row * QS_STR + c * 16;
        size_t go = (size_t)row * HDIM + c * 8;
        CP_ASYNC16(sQhi + so, Qhig + go);
        CP_ASYNC16(sQlo + so, Qlog + go);
    }
    CP_COMMIT();
    load_k(sKhi, sKlo, 0);
    load_v(0);
    CP_COMMIT();

    CP_WAIT(1); // Q visible (group0 done)
    __syncthreads();

    const uint32_t a_row = (uint32_t)(wm * 16 + ((lane >> 3) & 1) * 8 + (lane & 7));
    const uint32_t a_cb = (uint32_t)((lane >> 4) & 1) * 16;
    const uint32_t b_row = (uint32_t)(((lane >> 4) & 1) * 8 + (lane & 7));
    const uint32_t b_cb = (uint32_t)((lane >> 3) & 1) * 16;

    uint32_t qhi[8][4], qlo[8][4];
#pragma unroll
    for (int k16 = 0; k16 < 8; k16++) {
        LDSM_X4(qhi[k16][0], qhi[k16][1], qhi[k16][2], qhi[k16][3],
                sQhi + a_row * QS_STR + k16 * 32 + a_cb);
        LDSM_X4(qlo[k16][0], qlo[k16][1], qlo[k16][2], qlo[k16][3],
                sQlo + a_row * QS_STR + k16 * 32 + a_cb);
    }
    __syncthreads(); // Q region becomes K stage 1

    float o[16][4];
#pragma unroll
    for (int n = 0; n < 16; n++)
#pragma unroll
        for (int j = 0; j < 4; j++) o[n][j] = 0.0f;
    float m0r = -FLT_MAX, m1r = -FLT_MAX, l0 = 0.0f, l1 = 0.0f;

    const float scale = 0.08838834764831845f;
    const int rowg0 = q0 + wm * 16 + (lane >> 2);
    const int rowg1 = rowg0 + 8;

#pragma unroll 1
    for (int kt = 0; kt <= qb; kt++) {
        if (kt == 0) { CP_WAIT(0); } else { CP_WAIT(1); }
        __syncthreads();

        const uint32_t kcur_hi = (kt & 1) ? sQhi : sKhi;
        const uint32_t kcur_lo = (kt & 1) ? sQlo : sKlo;

        // ---- S = Q K^T (bf16x3) ----
        float s[8][4];
#pragma unroll
        for (int n = 0; n < 8; n++)
#pragma unroll
            for (int j = 0; j < 4; j++) s[n][j] = 0.0f;

#pragma unroll
        for (int k16 = 0; k16 < 8; k16++) {
            uint32_t bh[8][2], bl[8][2];
#pragma unroll
            for (int p = 0; p < 4; p++) {
                uint32_t r0, r1, r2, r3;
                LDSM_X4(r0, r1, r2, r3,
                        kcur_hi + (p * 16 + b_row) * QS_STR + k16 * 32 + b_cb);
                bh[2 * p][0] = r0; bh[2 * p][1] = r1;
                bh[2 * p + 1][0] = r2; bh[2 * p + 1][1] = r3;
                LDSM_X4(r0, r1, r2, r3,
                        kcur_lo + (p * 16 + b_row) * QS_STR + k16 * 32 + b_cb);
                bl[2 * p][0] = r0; bl[2 * p][1] = r1;
                bl[2 * p + 1][0] = r2; bl[2 * p + 1][1] = r3;
            }
#pragma unroll
            for (int n = 0; n < 8; n++) MMA16816(s[n], qhi[k16], bh[n]);
#pragma unroll
            for (int n = 0; n < 8; n++) MMA16816(s[n], qlo[k16], bh[n]);
#pragma unroll
            for (int n = 0; n < 8; n++) MMA16816(s[n], qhi[k16], bl[n]);
        }

        // prefetch K(kt+1) into alternate stage (hides behind softmax+PV)
        if (kt < qb) {
            load_k((kt & 1) ? sKhi : sQhi, (kt & 1) ? sKlo : sQlo, (kt + 1) * 64);
            CP_COMMIT();
        }

        // ---- scale + causal mask ----
#pragma unroll
        for (int n = 0; n < 8; n++)
#pragma unroll
            for (int j = 0; j < 4; j++) s[n][j] *= scale;
        if (kt == qb) {
            const int colb = kt * 64 + (lane & 3) * 2;
#pragma unroll
            for (int n = 0; n < 8; n++) {
#pragma unroll
                for (int e = 0; e < 2; e++) {
                    int col = colb + n * 8 + e;
                    if (col > rowg0) s[n][e] = -1e30f;
                    if (col > rowg1) s[n][2 + e] = -1e30f;
                }
            }
        }

        // ---- online softmax (registers + quad shfl) ----
        float mx0 = -FLT_MAX, mx1 = -FLT_MAX;
#pragma unroll
        for (int n = 0; n < 8; n++) {
            mx0 = fmaxf(mx0, fmaxf(s[n][0], s[n][1]));
            mx1 = fmaxf(mx1, fmaxf(s[n][2], s[n][3]));
        }
        mx0 = fmaxf(mx0, __shfl_xor_sync(0xffffffffu, mx0, 1));
        mx0 = fmaxf(mx0, __shfl_xor_sync(0xffffffffu, mx0, 2));
        mx1 = fmaxf(mx1, __shfl_xor_sync(0xffffffffu, mx1, 1));
        mx1 = fmaxf(mx1, __shfl_xor_sync(0xffffffffu, mx1, 2));
        float mn0 = fmaxf(m0r, mx0), mn1 = fmaxf(m1r, mx1);
        float corr0 = __expf(m0r - mn0), corr1 = __expf(m1r - mn1);
        m0r = mn0; m1r = mn1;

        float rs0 = 0.0f, rs1 = 0.0f;
#pragma unroll
        for (int n = 0; n < 8; n++) {
            s[n][0] = __expf(s[n][0] - mn0);
            s[n][1] = __expf(s[n][1] - mn0);
            s[n][2] = __expf(s[n][2] - mn1);
            s[n][3] = __expf(s[n][3] - mn1);
            rs0 += s[n][0] + s[n][1];
            rs1 += s[n][2] + s[n][3];
        }
        rs0 += __shfl_xor_sync(0xffffffffu, rs0, 1);
        rs0 += __shfl_xor_sync(0xffffffffu, rs0, 2);
        rs1 += __shfl_xor_sync(0xffffffffu, rs1, 1);
        rs1 += __shfl_xor_sync(0xffffffffu, rs1, 2);
        l0 = l0 * corr0 + rs0;
        l1 = l1 * corr1 + rs1;

#pragma unroll
        for (int n = 0; n < 16; n++) {
            o[n][0] *= corr0; o[n][1] *= corr0;
            o[n][2] *= corr1; o[n][3] *= corr1;
        }

        // V(kt) ready; K(kt+1) may still be in flight
        if (kt < qb) { CP_WAIT(1); } else { CP_WAIT(0); }
        __syncthreads();

        // ---- O += P V : P fp16 hi/lo x V fp16 (2 MMAs per tile) ----
#pragma unroll
        for (int j = 0; j < 4; j++) {
            uint32_t ah[4], al[4];
            split2h(s[2 * j][0], s[2 * j][1], ah[0], al[0]);
            split2h(s[2 * j][2], s[2 * j][3], ah[1], al[1]);
            split2h(s[2 * j + 1][0], s[2 * j + 1][1], ah[2], al[2]);
            split2h(s[2 * j + 1][2], s[2 * j + 1][3], ah[3], al[3]);
#pragma unroll
            for (int p = 0; p < 8; p++) {
                uint32_t r0, r1, r2, r3;
                LDSM_X4(r0, r1, r2, r3,
                        sVh + (p * 16 + b_row) * VT_STR + j * 32 + b_cb);
                uint32_t bh0[2] = {r0, r1}, bh1[2] = {r2, r3};
                MMAF16(o[2 * p], ah, bh0);
                MMAF16(o[2 * p + 1], ah, bh1);
                MMAF16(o[2 * p], al, bh0);
                MMAF16(o[2 * p + 1], al, bh1);
            }
        }

        __syncthreads(); // all warps done reading V before overwrite
        if (kt < qb) {
            load_v((kt + 1) * 64); // hides behind next iteration's S-MMA
            CP_COMMIT();
        }
    }

    // ---- epilogue: normalize, split hi/lo, write [b, s, h, d] ----
    float linv0 = 1.0f / l0, linv1 = 1.0f / l1;
    size_t base0 = (((size_t)b * SEQ + rowg0) * NHEAD + h) * HDIM + (lane & 3) * 2;
    size_t base1 = (((size_t)b * SEQ + rowg1) * NHEAD + h) * HDIM + (lane & 3) * 2;
#pragma unroll
    for (int n = 0; n < 16; n++) {
        uint32_t hi, lo;
        split2(o[n][0] * linv0, o[n][1] * linv0, hi, lo);
        *(uint32_t*)(g_ctx_hi + base0 + n * 8) = hi;
        *(uint32_t*)(g_ctx_lo + base0 + n * 8) = lo;
        split2(o[n][2] * linv1, o[n][3] * linv1, hi, lo);
        *(uint32_t*)(g_ctx_hi + base1 + n * 8) = hi;
        *(uint32_t*)(g_ctx_lo + base1 + n * 8) = lo;
    }
}

// ---------------------------------------------------------------------------
extern "C" void kernel_launch(void* const* d_in, const int* in_sizes, int n_in,
                              void* d_out, int out_size) {
    const float* hs = (const float*)d_in[0];
    const float* w_qkv = (const float*)d_in[1];
    const float* w_out = (const float*)d_in[2];
    const int* pos32 = (const int*)d_in[4];
    float* out = (float*)d_out;

    float* qkv;
    __nv_bfloat16 *hs_hi, *hs_lo, *wq_hi, *wq_lo, *wo_hi, *wo_lo, *cx_hi, *cx_lo;
    cudaGetSymbolAddress((void**)&qkv, g_qkv);
    cudaGetSymbolAddress((void**)&hs_hi, g_hs_hi);
    cudaGetSymbolAddress((void**)&hs_lo, g_hs_lo);
    cudaGetSymbolAddress((void**)&wq_hi, g_wqkv_hi);
    cudaGetSymbolAddress((void**)&wq_lo, g_wqkv_lo);
    cudaGetSymbolAddress((void**)&wo_hi, g_wout_hi);
    cudaGetSymbolAddress((void**)&wo_lo, g_wout_lo);
    cudaGetSymbolAddress((void**)&cx_hi, g_ctx_hi);
    cudaGetSymbolAddress((void**)&cx_lo, g_ctx_lo);

    cudaFuncSetAttribute(gemm_hmma4<QKVN, HIDN>,
                         cudaFuncAttributeMaxDynamicSharedMemorySize, GEMM2_SMEM);
    cudaFuncSetAttribute(gemm_hmma4<HIDN, HIDN>,
                         cudaFuncAttributeMaxDynamicSharedMemorySize, GEMM2_SMEM);
    cudaFuncSetAttribute(attn_hmma, cudaFuncAttributeMaxDynamicSharedMemorySize,
                         ATTN_SMEM);

    // 0. bf16 hi/lo splits of inputs
    {
        int n4;
        n4 = (MROWS * HIDN) / 4;
        split_kernel<<<(n4 + 255) / 256, 256>>>((const float4*)hs,
                                                (__nv_bfloat162*)hs_hi,
                                                (__nv_bfloat162*)hs_lo, n4);
        n4 = (QKVN * HIDN) / 4;
        split_kernel<<<(n4 + 255) / 256, 256>>>((const float4*)w_qkv,
                                                (__nv_bfloat162*)wq_hi,
                                                (__nv_bfloat162*)wq_lo, n4);
        n4 = (HIDN * HIDN) / 4;
        split_kernel<<<(n4 + 255) / 256, 256>>>((const float4*)w_out,
                                                (__nv_bfloat162*)wo_hi,
                                                (__nv_bfloat162*)wo_lo, n4);
    }

    // 1. QKV GEMM (HMMA bf16x3)
    {
        dim3 grid(QKVN / 128, MROWS / 128);
        gemm_hmma4<QKVN, HIDN><<<grid, 128, GEMM2_SMEM>>>(hs_hi, hs_lo, wq_hi,
                                                          wq_lo, qkv);
    }

    // 2. RoPE + scatter; V fp16 transpose
    rope_q_kernel<<<(BSZ * SEQ * NHEAD * 64) / 256, 256>>>(pos32);
    rope_k_kernel<<<(BSZ * SEQ * NKVH * 64) / 256, 256>>>(pos32);
    {
        dim3 grid(SEQ / 64, (HDIM / 32) * NKVH, BSZ);
        vt_split_kernel<<<grid, 256>>>();
    }

    // 3. Flash attention (QK bf16x3, PV fp16x2, pipelined K/V)
    {
        dim3 grid(SEQ / 64, NHEAD, BSZ);
        attn_hmma<<<grid, 128, ATTN_SMEM>>>();
    }

    // 4. Output GEMM (HMMA bf16x3)
    {
        dim3 grid(HIDN / 128, MROWS / 128);
        gemm_hmma4<HIDN, HIDN><<<grid, 128, GEMM2_SMEM>>>(cx_hi, cx_lo, wo_hi,
                                                          wo_lo, out);
    }
}

// round 16
// speedup vs baseline: 1.2862x; 1.1936x over previous
#include <cuda_runtime.h>
#include <cuda_bf16.h>
#include <cuda_fp16.h>
#include <math.h>
#include <float.h>
#include <stdint.h>

#define BSZ 2
#define SEQ 2048
#define HIDN 2048
#define NHEAD 16
#define NKVH 4
#define HDIM 128
#define NREP (NHEAD / NKVH)
#define QKVN (HIDN + 2 * NKVH * HDIM) /* 3072 */
#define MROWS (BSZ * SEQ)             /* 4096 */

// ---------------------------------------------------------------------------
// Scratch (static device globals; no runtime allocation allowed)
// ---------------------------------------------------------------------------
__device__ float g_qkv[(size_t)MROWS * QKVN];

// fp16 operands for projection GEMMs (A = hi/lo split, W = single fp16)
__device__ __half g_hs_hi[(size_t)MROWS * HIDN];
__device__ __half g_hs_lo[(size_t)MROWS * HIDN];
__device__ __half g_wqkv_h[(size_t)QKVN * HIDN];
__device__ __half g_wout_h[(size_t)HIDN * HIDN];
__device__ __half g_ctx_hi[(size_t)MROWS * HIDN];
__device__ __half g_ctx_lo[(size_t)MROWS * HIDN];

// attention operands (QK stays bf16x3)
__device__ __nv_bfloat16 g_q_hi[(size_t)BSZ * NHEAD * SEQ * HDIM];
__device__ __nv_bfloat16 g_q_lo[(size_t)BSZ * NHEAD * SEQ * HDIM];
__device__ __nv_bfloat16 g_k_hi[(size_t)BSZ * NKVH * SEQ * HDIM];
__device__ __nv_bfloat16 g_k_lo[(size_t)BSZ * NKVH * SEQ * HDIM];
// V pre-transposed, single fp16: [b][hk][d][SEQ]
__device__ __half g_vt_h[(size_t)BSZ * NKVH * HDIM * SEQ];

// ---------------------------------------------------------------------------
// Portable tensor-core primitives (baseline PTX, valid on plain sm_103)
// ---------------------------------------------------------------------------
__device__ __forceinline__ uint32_t smem_u32(const void* p) {
    uint32_t a;
    asm("{ .reg .u64 t; cvta.to.shared.u64 t, %1; cvt.u32.u64 %0, t; }"
        : "=r"(a) : "l"(p));
    return a;
}

#define LDSM_X4(r0, r1, r2, r3, addr)                                          \
    asm volatile(                                                              \
        "ldmatrix.sync.aligned.m8n8.x4.shared.b16 {%0,%1,%2,%3}, [%4];"        \
        : "=r"(r0), "=r"(r1), "=r"(r2), "=r"(r3) : "r"(addr))

#define MMA16816(c, a, b)                                                      \
    asm volatile(                                                              \
        "mma.sync.aligned.m16n8k16.row.col.f32.bf16.bf16.f32 "                 \
        "{%0,%1,%2,%3}, {%4,%5,%6,%7}, {%8,%9}, {%0,%1,%2,%3};"                \
        : "+f"((c)[0]), "+f"((c)[1]), "+f"((c)[2]), "+f"((c)[3])               \
        : "r"((a)[0]), "r"((a)[1]), "r"((a)[2]), "r"((a)[3]),                  \
          "r"((b)[0]), "r"((b)[1]))

#define MMAF16(c, a, b)                                                        \
    asm volatile(                                                              \
        "mma.sync.aligned.m16n8k16.row.col.f32.f16.f16.f32 "                   \
        "{%0,%1,%2,%3}, {%4,%5,%6,%7}, {%8,%9}, {%0,%1,%2,%3};"                \
        : "+f"((c)[0]), "+f"((c)[1]), "+f"((c)[2]), "+f"((c)[3])               \
        : "r"((a)[0]), "r"((a)[1]), "r"((a)[2]), "r"((a)[3]),                  \
          "r"((b)[0]), "r"((b)[1]))

#define CP_ASYNC16(dst, src)                                                   \
    asm volatile("cp.async.cg.shared.global [%0], [%1], 16;"                   \
                 :: "r"(dst), "l"(src) : "memory")
#define CP_COMMIT() asm volatile("cp.async.commit_group;" ::: "memory")
#define CP_WAIT(n) asm volatile("cp.async.wait_group %0;" :: "n"(n) : "memory")

__device__ __forceinline__ void split2(float x, float y, uint32_t& hi,
                                       uint32_t& lo) {
    __nv_bfloat16 hx = __float2bfloat16(x), hy = __float2bfloat16(y);
    __nv_bfloat16 lx = __float2bfloat16(x - __bfloat162float(hx));
    __nv_bfloat16 ly = __float2bfloat16(y - __bfloat162float(hy));
    __nv_bfloat162 h2 = __halves2bfloat162(hx, hy);
    __nv_bfloat162 l2 = __halves2bfloat162(lx, ly);
    hi = *(uint32_t*)&h2;
    lo = *(uint32_t*)&l2;
}

// fp16 hi/lo split of a float pair
__device__ __forceinline__ void split2h(float x, float y, uint32_t& hi,
                                        uint32_t& lo) {
    __half hx = __float2half_rn(x), hy = __float2half_rn(y);
    __half lx = __float2half_rn(x - __half2float(hx));
    __half ly = __float2half_rn(y - __half2float(hy));
    __half2 h2 = __halves2half2(hx, hy);
    __half2 l2 = __halves2half2(lx, ly);
    hi = *(uint32_t*)&h2;
    lo = *(uint32_t*)&l2;
}

// ---------------------------------------------------------------------------
// fp32 -> (fp16 hi, fp16 lo) split, 4 elems/thread
// ---------------------------------------------------------------------------
__global__ void split_h_kernel(const float4* __restrict__ src,
                               __half2* __restrict__ hi,
                               __half2* __restrict__ lo, int n4) {
    int i = blockIdx.x * blockDim.x + threadIdx.x;
    if (i >= n4) return;
    float4 x = src[i];
    uint32_t h0, l0, h1, l1;
    split2h(x.x, x.y, h0, l0);
    split2h(x.z, x.w, h1, l1);
    ((uint32_t*)hi)[2 * i] = h0;
    ((uint32_t*)hi)[2 * i + 1] = h1;
    ((uint32_t*)lo)[2 * i] = l0;
    ((uint32_t*)lo)[2 * i + 1] = l1;
}

// fp32 -> fp16 convert, 4 elems/thread
__global__ void conv_h_kernel(const float4* __restrict__ src,
                              __half2* __restrict__ dst, int n4) {
    int i = blockIdx.x * blockDim.x + threadIdx.x;
    if (i >= n4) return;
    float4 x = src[i];
    dst[2 * i] = __halves2half2(__float2half_rn(x.x), __float2half_rn(x.y));
    dst[2 * i + 1] = __halves2half2(__float2half_rn(x.z), __float2half_rn(x.w));
}

// ---------------------------------------------------------------------------
// fp16x2 HMMA GEMM v5: C[M,N] = A[M,K] @ W[N,K]^T.
// A = fp16 hi/lo split (2 tiles), W = single fp16 (1 tile). 2 MMA products.
// 128 threads (4 warps 2x2), warp tile 64x64, cp.async double-buffered.
// ---------------------------------------------------------------------------
#define SROW2 80
#define TILE2 (128 * SROW2)      /* 10240 */
#define STAGE5 (3 * TILE2)       /* 30720 */
#define GEMM5_SMEM (2 * STAGE5)  /* 61440 */

template <int N, int K>
__global__ __launch_bounds__(128) void gemm_hmma5(
    const __half* __restrict__ a_hi, const __half* __restrict__ a_lo,
    const __half* __restrict__ w_h, float* __restrict__ C) {
    constexpr int NCH = K / 32;

    extern __shared__ __align__(16) char sm2[];
    const uint32_t sb = smem_u32(sm2);

    const int tid = threadIdx.x;
    const int lane = tid & 31;
    const int warp = tid >> 5;
    const int wm = warp >> 1;
    const int wn = warp & 1;
    const int m0 = blockIdx.y * 128;
    const int n0 = blockIdx.x * 128;

    auto stage_load = [&](int buf, int kk) {
        const uint32_t dst = sb + buf * STAGE5;
#pragma unroll
        for (int i = 0; i < 4; i++) {
            int lin = tid + i * 128;
            int row = lin >> 2;
            int c16 = lin & 3;
            uint32_t so = (uint32_t)row * SROW2 + c16 * 16;
            size_t ga = (size_t)(m0 + row) * K + kk + c16 * 8;
            size_t gw = (size_t)(n0 + row) * K + kk + c16 * 8;
            CP_ASYNC16(dst + 0 * TILE2 + so, a_hi + ga);
            CP_ASYNC16(dst + 1 * TILE2 + so, a_lo + ga);
            CP_ASYNC16(dst + 2 * TILE2 + so, w_h + gw);
        }
    };

    float acc[4][8][4];
#pragma unroll
    for (int t = 0; t < 4; t++)
#pragma unroll
        for (int n = 0; n < 8; n++)
#pragma unroll
            for (int j = 0; j < 4; j++) acc[t][n][j] = 0.0f;

    const uint32_t a_row = (uint32_t)(wm * 64 + ((lane >> 3) & 1) * 8 + (lane & 7));
    const uint32_t a_cb = (uint32_t)((lane >> 4) & 1) * 16;
    const uint32_t b_row = (uint32_t)(wn * 64 + ((lane >> 4) & 1) * 8 + (lane & 7));
    const uint32_t b_cb = (uint32_t)((lane >> 3) & 1) * 16;

    stage_load(0, 0);
    CP_COMMIT();

#pragma unroll 1
    for (int c = 0; c < NCH; c++) {
        if (c + 1 < NCH) {
            stage_load((c + 1) & 1, (c + 1) * 32);
            CP_COMMIT();
            CP_WAIT(1);
        } else {
            CP_WAIT(0);
        }
        __syncthreads();

        const uint32_t st = sb + (c & 1) * STAGE5;
        const uint32_t sAhi = st, sAlo = st + TILE2;
        const uint32_t sW = st + 2 * TILE2;

#pragma unroll
        for (int k16 = 0; k16 < 2; k16++) {
            const uint32_t kb = (uint32_t)k16 * 32;
            uint32_t ah[4][4], al[4][4];
#pragma unroll
            for (int t = 0; t < 4; t++) {
                LDSM_X4(ah[t][0], ah[t][1], ah[t][2], ah[t][3],
                        sAhi + (a_row + t * 16) * SROW2 + kb + a_cb);
                LDSM_X4(al[t][0], al[t][1], al[t][2], al[t][3],
                        sAlo + (a_row + t * 16) * SROW2 + kb + a_cb);
            }
            uint32_t bh[8][2];
#pragma unroll
            for (int p = 0; p < 4; p++) {
                uint32_t r0, r1, r2, r3;
                LDSM_X4(r0, r1, r2, r3,
                        sW + (b_row + p * 16) * SROW2 + kb + b_cb);
                bh[2 * p][0] = r0; bh[2 * p][1] = r1;
                bh[2 * p + 1][0] = r2; bh[2 * p + 1][1] = r3;
            }
            // product-major: hi*w then lo*w
#pragma unroll
            for (int t = 0; t < 4; t++)
#pragma unroll
                for (int n = 0; n < 8; n++) MMAF16(acc[t][n], ah[t], bh[n]);
#pragma unroll
            for (int t = 0; t < 4; t++)
#pragma unroll
                for (int n = 0; n < 8; n++) MMAF16(acc[t][n], al[t], bh[n]);
        }
        __syncthreads();
    }

#pragma unroll
    for (int t = 0; t < 4; t++) {
        int r0 = m0 + wm * 64 + t * 16 + (lane >> 2);
#pragma unroll
        for (int n = 0; n < 8; n++) {
            int col = n0 + wn * 64 + n * 8 + (lane & 3) * 2;
            *(float2*)&C[(size_t)r0 * N + col] = make_float2(acc[t][n][0], acc[t][n][1]);
            *(float2*)&C[(size_t)(r0 + 8) * N + col] = make_float2(acc[t][n][2], acc[t][n][3]);
        }
    }
}

// ---------------------------------------------------------------------------
// Position read: robust to int32 vs int64 storage of position_ids (arange).
// ---------------------------------------------------------------------------
__device__ __forceinline__ int read_pos(const int* __restrict__ pos32, int n) {
    bool is64 = (pos32[1] == 0);
    return pos32[is64 ? 2 * n : n];
}

// RoPE + scatter + bf16 hi/lo split (QK precision path unchanged)
__global__ void rope_q_kernel(const int* __restrict__ pos32) {
    int idx = blockIdx.x * blockDim.x + threadIdx.x;
    int d = idx & 63;
    int h = (idx >> 6) & (NHEAD - 1);
    int s = (idx >> 10) & (SEQ - 1);
    int b = idx >> 21;

    int p = read_pos(pos32, b * SEQ + s);
    float invf = (float)exp(-((double)d / 64.0) * 9.210340371976184);
    float ang = (float)p * invf;
    float sn, c;
    sincosf(ang, &sn, &c);

    const float* src = g_qkv + ((size_t)b * SEQ + s) * QKVN + h * HDIM;
    float x1 = src[d], x2 = src[d + 64];
    float y1 = x1 * c - x2 * sn;
    float y2 = x2 * c + x1 * sn;

    size_t o = (((size_t)(b * NHEAD + h)) * SEQ + s) * HDIM;
    __nv_bfloat16 h1 = __float2bfloat16(y1);
    __nv_bfloat16 h2 = __float2bfloat16(y2);
    g_q_hi[o + d] = h1;
    g_q_hi[o + d + 64] = h2;
    g_q_lo[o + d] = __float2bfloat16(y1 - __bfloat162float(h1));
    g_q_lo[o + d + 64] = __float2bfloat16(y2 - __bfloat162float(h2));
}

__global__ void rope_k_kernel(const int* __restrict__ pos32) {
    int idx = blockIdx.x * blockDim.x + threadIdx.x;
    int d = idx & 63;
    int h = (idx >> 6) & (NKVH - 1);
    int s = (idx >> 8) & (SEQ - 1);
    int b = idx >> 19;

    int p = read_pos(pos32, b * SEQ + s);
    float invf = (float)exp(-((double)d / 64.0) * 9.210340371976184);
    float ang = (float)p * invf;
    float sn, c;
    sincosf(ang, &sn, &c);

    const float* src = g_qkv + ((size_t)b * SEQ + s) * QKVN + HIDN + h * HDIM;
    float x1 = src[d], x2 = src[d + 64];
    float y1 = x1 * c - x2 * sn;
    float y2 = x2 * c + x1 * sn;

    size_t o = (((size_t)(b * NKVH + h)) * SEQ + s) * HDIM;
    __nv_bfloat16 h1 = __float2bfloat16(y1);
    __nv_bfloat16 h2 = __float2bfloat16(y2);
    g_k_hi[o + d] = h1;
    g_k_hi[o + d + 64] = h2;
    g_k_lo[o + d] = __float2bfloat16(y1 - __bfloat162float(h1));
    g_k_lo[o + d + 64] = __float2bfloat16(y2 - __bfloat162float(h2));
}

// ---------------------------------------------------------------------------
// V fp16 + transpose to [b][hk][d][SEQ].
// ---------------------------------------------------------------------------
__global__ void vt_split_kernel() {
    __shared__ __half th[32][72];
    const int s0 = blockIdx.x * 64;
    const int hk = blockIdx.y >> 2;
    const int d0 = (blockIdx.y & 3) * 32;
    const int b = blockIdx.z;
    const int t = threadIdx.x;

#pragma unroll
    for (int i = 0; i < 8; i++) {
        int s = (t >> 5) + i * 8;
        int d = t & 31;
        float x = g_qkv[((size_t)b * SEQ + s0 + s) * QKVN + HIDN + NKVH * HDIM +
                        hk * HDIM + d0 + d];
        th[d][s] = __float2half_rn(x);
    }
    __syncthreads();

    int d = t >> 3, c8 = (t & 7) * 8;
    size_t o = (((size_t)(b * NKVH + hk)) * HDIM + d0 + d) * SEQ + s0 + c8;
    *(uint4*)(g_vt_h + o) = *(uint4*)&th[d][c8];
}

// ---------------------------------------------------------------------------
// Flash attention: QK^T bf16x3 + PV fp16x2; pipelined K/V loads.
// Epilogue emits fp16 hi/lo ctx (feeds fp16 out GEMM).
// ---------------------------------------------------------------------------
#define QS_STR 272
#define VT_STR 144
#define ATTN_SMEM (4 * 64 * QS_STR + 128 * VT_STR) /* 88064 */

__global__ __launch_bounds__(128, 2) void attn_hmma() {
    extern __shared__ __align__(16) char smr[];
    const uint32_t sbase = smem_u32(smr);
    const uint32_t sQhi = sbase;
    const uint32_t sQlo = sQhi + 64 * QS_STR;
    const uint32_t sKhi = sQlo + 64 * QS_STR;
    const uint32_t sKlo = sKhi + 64 * QS_STR;
    const uint32_t sVh = sKlo + 64 * QS_STR;

    const int tid = threadIdx.x;
    const int lane = tid & 31;
    const int wm = tid >> 5;
    const int qb = gridDim.x - 1 - blockIdx.x; // heaviest first
    const int h = blockIdx.y;
    const int b = blockIdx.z;
    const int q0 = qb * 64;
    const int hk = h / NREP;

    const __nv_bfloat16* Qhig = g_q_hi + (((size_t)(b * NHEAD + h)) * SEQ + q0) * HDIM;
    const __nv_bfloat16* Qlog = g_q_lo + (((size_t)(b * NHEAD + h)) * SEQ + q0) * HDIM;
    const __nv_bfloat16* Khig = g_k_hi + ((size_t)(b * NKVH + hk)) * SEQ * HDIM;
    const __nv_bfloat16* Klog = g_k_lo + ((size_t)(b * NKVH + hk)) * SEQ * HDIM;
    const __half* Vthg = g_vt_h + ((size_t)(b * NKVH + hk)) * HDIM * SEQ;

    auto load_k = [&](uint32_t dhi, uint32_t dlo, int k0) {
#pragma unroll
        for (int i = 0; i < 8; i++) {
            int lin = tid + i * 128;
            int row = lin >> 4, c = lin & 15;
            uint32_t so = (uint32_t)row * QS_STR + c * 16;
            size_t go = (size_t)(k0 + row) * HDIM + c * 8;
            CP_ASYNC16(dhi + so, Khig + go);
            CP_ASYNC16(dlo + so, Klog + go);
        }
    };
    auto load_v = [&](int k0) {
#pragma unroll
        for (int i = 0; i < 8; i++) {
            int lin = tid + i * 128;
            int row = lin >> 3, c = lin & 7;
            uint32_t so = (uint32_t)row * VT_STR + c * 16;
            size_t go = (size_t)row * SEQ + k0 + c * 8;
            CP_ASYNC16(sVh + so, Vthg + go);
        }
    };

    // prologue: group0 = Q tiles, group1 = K0 + V0
#pragma unroll
    for (int i = 0; i < 8; i++) {
        int lin = tid + i * 128;
        int row = lin >> 4, c = lin & 15;
        uint32_t so = (uint32_t)row * QS_STR + c * 16;
        size_t go = (size_t)row * HDIM + c * 8;
        CP_ASYNC16(sQhi + so, Qhig + go);
        CP_ASYNC16(sQlo + so, Qlog + go);
    }
    CP_COMMIT();
    load_k(sKhi, sKlo, 0);
    load_v(0);
    CP_COMMIT();

    CP_WAIT(1);
    __syncthreads();

    const uint32_t a_row = (uint32_t)(wm * 16 + ((lane >> 3) & 1) * 8 + (lane & 7));
    const uint32_t a_cb = (uint32_t)((lane >> 4) & 1) * 16;
    const uint32_t b_row = (uint32_t)(((lane >> 4) & 1) * 8 + (lane & 7));
    const uint32_t b_cb = (uint32_t)((lane >> 3) & 1) * 16;

    uint32_t qhi[8][4], qlo[8][4];
#pragma unroll
    for (int k16 = 0; k16 < 8; k16++) {
        LDSM_X4(qhi[k16][0], qhi[k16][1], qhi[k16][2], qhi[k16][3],
                sQhi + a_row * QS_STR + k16 * 32 + a_cb);
        LDSM_X4(qlo[k16][0], qlo[k16][1], qlo[k16][2], qlo[k16][3],
                sQlo + a_row * QS_STR + k16 * 32 + a_cb);
    }
    __syncthreads(); // Q region becomes K stage 1

    float o[16][4];
#pragma unroll
    for (int n = 0; n < 16; n++)
#pragma unroll
        for (int j = 0; j < 4; j++) o[n][j] = 0.0f;
    float m0r = -FLT_MAX, m1r = -FLT_MAX, l0 = 0.0f, l1 = 0.0f;

    const float scale = 0.08838834764831845f;
    const int rowg0 = q0 + wm * 16 + (lane >> 2);
    const int rowg1 = rowg0 + 8;

#pragma unroll 1
    for (int kt = 0; kt <= qb; kt++) {
        if (kt == 0) { CP_WAIT(0); } else { CP_WAIT(1); }
        __syncthreads();

        const uint32_t kcur_hi = (kt & 1) ? sQhi : sKhi;
        const uint32_t kcur_lo = (kt & 1) ? sQlo : sKlo;

        // ---- S = Q K^T (bf16x3) ----
        float s[8][4];
#pragma unroll
        for (int n = 0; n < 8; n++)
#pragma unroll
            for (int j = 0; j < 4; j++) s[n][j] = 0.0f;

#pragma unroll
        for (int k16 = 0; k16 < 8; k16++) {
            uint32_t bh[8][2], bl[8][2];
#pragma unroll
            for (int p = 0; p < 4; p++) {
                uint32_t r0, r1, r2, r3;
                LDSM_X4(r0, r1, r2, r3,
                        kcur_hi + (p * 16 + b_row) * QS_STR + k16 * 32 + b_cb);
                bh[2 * p][0] = r0; bh[2 * p][1] = r1;
                bh[2 * p + 1][0] = r2; bh[2 * p + 1][1] = r3;
                LDSM_X4(r0, r1, r2, r3,
                        kcur_lo + (p * 16 + b_row) * QS_STR + k16 * 32 + b_cb);
                bl[2 * p][0] = r0; bl[2 * p][1] = r1;
                bl[2 * p + 1][0] = r2; bl[2 * p + 1][1] = r3;
            }
#pragma unroll
            for (int n = 0; n < 8; n++) MMA16816(s[n], qhi[k16], bh[n]);
#pragma unroll
            for (int n = 0; n < 8; n++) MMA16816(s[n], qlo[k16], bh[n]);
#pragma unroll
            for (int n = 0; n < 8; n++) MMA16816(s[n], qhi[k16], bl[n]);
        }

        if (kt < qb) {
            load_k((kt & 1) ? sKhi : sQhi, (kt & 1) ? sKlo : sQlo, (kt + 1) * 64);
            CP_COMMIT();
        }

        // ---- scale + causal mask ----
#pragma unroll
        for (int n = 0; n < 8; n++)
#pragma unroll
            for (int j = 0; j < 4; j++) s[n][j] *= scale;
        if (kt == qb) {
            const int colb = kt * 64 + (lane & 3) * 2;
#pragma unroll
            for (int n = 0; n < 8; n++) {
#pragma unroll
                for (int e = 0; e < 2; e++) {
                    int col = colb + n * 8 + e;
                    if (col > rowg0) s[n][e] = -1e30f;
                    if (col > rowg1) s[n][2 + e] = -1e30f;
                }
            }
        }

        // ---- online softmax ----
        float mx0 = -FLT_MAX, mx1 = -FLT_MAX;
#pragma unroll
        for (int n = 0; n < 8; n++) {
            mx0 = fmaxf(mx0, fmaxf(s[n][0], s[n][1]));
            mx1 = fmaxf(mx1, fmaxf(s[n][2], s[n][3]));
        }
        mx0 = fmaxf(mx0, __shfl_xor_sync(0xffffffffu, mx0, 1));
        mx0 = fmaxf(mx0, __shfl_xor_sync(0xffffffffu, mx0, 2));
        mx1 = fmaxf(mx1, __shfl_xor_sync(0xffffffffu, mx1, 1));
        mx1 = fmaxf(mx1, __shfl_xor_sync(0xffffffffu, mx1, 2));
        float mn0 = fmaxf(m0r, mx0), mn1 = fmaxf(m1r, mx1);
        float corr0 = __expf(m0r - mn0), corr1 = __expf(m1r - mn1);
        m0r = mn0; m1r = mn1;

        float rs0 = 0.0f, rs1 = 0.0f;
#pragma unroll
        for (int n = 0; n < 8; n++) {
            s[n][0] = __expf(s[n][0] - mn0);
            s[n][1] = __expf(s[n][1] - mn0);
            s[n][2] = __expf(s[n][2] - mn1);
            s[n][3] = __expf(s[n][3] - mn1);
            rs0 += s[n][0] + s[n][1];
            rs1 += s[n][2] + s[n][3];
        }
        rs0 += __shfl_xor_sync(0xffffffffu, rs0, 1);
        rs0 += __shfl_xor_sync(0xffffffffu, rs0, 2);
        rs1 += __shfl_xor_sync(0xffffffffu, rs1, 1);
        rs1 += __shfl_xor_sync(0xffffffffu, rs1, 2);
        l0 = l0 * corr0 + rs0;
        l1 = l1 * corr1 + rs1;

#pragma unroll
        for (int n = 0; n < 16; n++) {
            o[n][0] *= corr0; o[n][1] *= corr0;
            o[n][2] *= corr1; o[n][3] *= corr1;
        }

        if (kt < qb) { CP_WAIT(1); } else { CP_WAIT(0); }
        __syncthreads();

        // ---- O += P V : P fp16 hi/lo x V fp16 ----
#pragma unroll
        for (int j = 0; j < 4; j++) {
            uint32_t ah[4], al[4];
            split2h(s[2 * j][0], s[2 * j][1], ah[0], al[0]);
            split2h(s[2 * j][2], s[2 * j][3], ah[1], al[1]);
            split2h(s[2 * j + 1][0], s[2 * j + 1][1], ah[2], al[2]);
            split2h(s[2 * j + 1][2], s[2 * j + 1][3], ah[3], al[3]);
#pragma unroll
            for (int p = 0; p < 8; p++) {
                uint32_t r0, r1, r2, r3;
                LDSM_X4(r0, r1, r2, r3,
                        sVh + (p * 16 + b_row) * VT_STR + j * 32 + b_cb);
                uint32_t bh0[2] = {r0, r1}, bh1[2] = {r2, r3};
                MMAF16(o[2 * p], ah, bh0);
                MMAF16(o[2 * p + 1], ah, bh1);
                MMAF16(o[2 * p], al, bh0);
                MMAF16(o[2 * p + 1], al, bh1);
            }
        }

        __syncthreads();
        if (kt < qb) {
            load_v((kt + 1) * 64);
            CP_COMMIT();
        }
    }

    // ---- epilogue: normalize, fp16 hi/lo split, write [b, s, h, d] ----
    float linv0 = 1.0f / l0, linv1 = 1.0f / l1;
    size_t base0 = (((size_t)b * SEQ + rowg0) * NHEAD + h) * HDIM + (lane & 3) * 2;
    size_t base1 = (((size_t)b * SEQ + rowg1) * NHEAD + h) * HDIM + (lane & 3) * 2;
#pragma unroll
    for (int n = 0; n < 16; n++) {
        uint32_t hi, lo;
        split2h(o[n][0] * linv0, o[n][1] * linv0, hi, lo);
        *(uint32_t*)(g_ctx_hi + base0 + n * 8) = hi;
        *(uint32_t*)(g_ctx_lo + base0 + n * 8) = lo;
        split2h(o[n][2] * linv1, o[n][3] * linv1, hi, lo);
        *(uint32_t*)(g_ctx_hi + base1 + n * 8) = hi;
        *(uint32_t*)(g_ctx_lo + base1 + n * 8) = lo;
    }
}

// ---------------------------------------------------------------------------
extern "C" void kernel_launch(void* const* d_in, const int* in_sizes, int n_in,
                              void* d_out, int out_size) {
    const float* hs = (const float*)d_in[0];
    const float* w_qkv = (const float*)d_in[1];
    const float* w_out = (const float*)d_in[2];
    const int* pos32 = (const int*)d_in[4];
    float* out = (float*)d_out;

    float* qkv;
    __half *hs_hi, *hs_lo, *wq_h, *wo_h, *cx_hi, *cx_lo;
    cudaGetSymbolAddress((void**)&qkv, g_qkv);
    cudaGetSymbolAddress((void**)&hs_hi, g_hs_hi);
    cudaGetSymbolAddress((void**)&hs_lo, g_hs_lo);
    cudaGetSymbolAddress((void**)&wq_h, g_wqkv_h);
    cudaGetSymbolAddress((void**)&wo_h, g_wout_h);
    cudaGetSymbolAddress((void**)&cx_hi, g_ctx_hi);
    cudaGetSymbolAddress((void**)&cx_lo, g_ctx_lo);

    cudaFuncSetAttribute(gemm_hmma5<QKVN, HIDN>,
                         cudaFuncAttributeMaxDynamicSharedMemorySize, GEMM5_SMEM);
    cudaFuncSetAttribute(gemm_hmma5<HIDN, HIDN>,
                         cudaFuncAttributeMaxDynamicSharedMemorySize, GEMM5_SMEM);
    cudaFuncSetAttribute(attn_hmma, cudaFuncAttributeMaxDynamicSharedMemorySize,
                         ATTN_SMEM);

    // 0. fp16 operand prep
    {
        int n4;
        n4 = (MROWS * HIDN) / 4;
        split_h_kernel<<<(n4 + 255) / 256, 256>>>((const float4*)hs,
                                                  (__half2*)hs_hi,
                                                  (__half2*)hs_lo, n4);
        n4 = (QKVN * HIDN) / 4;
        conv_h_kernel<<<(n4 + 255) / 256, 256>>>((const float4*)w_qkv,
                                                 (__half2*)wq_h, n4);
        n4 = (HIDN * HIDN) / 4;
        conv_h_kernel<<<(n4 + 255) / 256, 256>>>((const float4*)w_out,
                                                 (__half2*)wo_h, n4);
    }

    // 1. QKV GEMM (HMMA fp16x2)
    {
        dim3 grid(QKVN / 128, MROWS / 128);
        gemm_hmma5<QKVN, HIDN><<<grid, 128, GEMM5_SMEM>>>(hs_hi, hs_lo, wq_h,
                                                          qkv);
    }

    // 2. RoPE + scatter (bf16); V fp16 transpose
    rope_q_kernel<<<(BSZ * SEQ * NHEAD * 64) / 256, 256>>>(pos32);
    rope_k_kernel<<<(BSZ * SEQ * NKVH * 64) / 256, 256>>>(pos32);
    {
        dim3 grid(SEQ / 64, (HDIM / 32) * NKVH, BSZ);
        vt_split_kernel<<<grid, 256>>>();
    }

    // 3. Flash attention (QK bf16x3, PV fp16x2, pipelined K/V)
    {
        dim3 grid(SEQ / 64, NHEAD, BSZ);
        attn_hmma<<<grid, 128, ATTN_SMEM>>>();
    }

    // 4. Output GEMM (HMMA fp16x2)
    {
        dim3 grid(HIDN / 128, MROWS / 128);
        gemm_hmma5<HIDN, HIDN><<<grid, 128, GEMM5_SMEM>>>(cx_hi, cx_lo, wo_h,
                                                          out);
    }
}

// round 17
// speedup vs baseline: 1.3881x; 1.0792x over previous
#include <cuda_runtime.h>
#include <cuda_bf16.h>
#include <cuda_fp16.h>
#include <math.h>
#include <float.h>
#include <stdint.h>

#define BSZ 2
#define SEQ 2048
#define HIDN 2048
#define NHEAD 16
#define NKVH 4
#define HDIM 128
#define NREP (NHEAD / NKVH)
#define QKVN (HIDN + 2 * NKVH * HDIM) /* 3072 */
#define MROWS (BSZ * SEQ)             /* 4096 */

// ---------------------------------------------------------------------------
// Scratch (static device globals; no runtime allocation allowed)
// ---------------------------------------------------------------------------
__device__ float g_qkv[(size_t)MROWS * QKVN];

// fp16 operands for projection GEMMs (A = hi/lo split, W = single fp16)
__device__ __half g_hs_hi[(size_t)MROWS * HIDN];
__device__ __half g_hs_lo[(size_t)MROWS * HIDN];
__device__ __half g_wqkv_h[(size_t)QKVN * HIDN];
__device__ __half g_wout_h[(size_t)HIDN * HIDN];
__device__ __half g_ctx_hi[(size_t)MROWS * HIDN];
__device__ __half g_ctx_lo[(size_t)MROWS * HIDN];

// attention operands: Q fp16 hi/lo, K single fp16, V single fp16 (transposed)
__device__ __half g_q_hi[(size_t)BSZ * NHEAD * SEQ * HDIM];
__device__ __half g_q_lo[(size_t)BSZ * NHEAD * SEQ * HDIM];
__device__ __half g_k_h[(size_t)BSZ * NKVH * SEQ * HDIM];
__device__ __half g_vt_h[(size_t)BSZ * NKVH * HDIM * SEQ];

// ---------------------------------------------------------------------------
// Portable tensor-core primitives (baseline PTX, valid on plain sm_103)
// ---------------------------------------------------------------------------
__device__ __forceinline__ uint32_t smem_u32(const void* p) {
    uint32_t a;
    asm("{ .reg .u64 t; cvta.to.shared.u64 t, %1; cvt.u32.u64 %0, t; }"
        : "=r"(a) : "l"(p));
    return a;
}

#define LDSM_X4(r0, r1, r2, r3, addr)                                          \
    asm volatile(                                                              \
        "ldmatrix.sync.aligned.m8n8.x4.shared.b16 {%0,%1,%2,%3}, [%4];"        \
        : "=r"(r0), "=r"(r1), "=r"(r2), "=r"(r3) : "r"(addr))

#define MMAF16(c, a, b)                                                        \
    asm volatile(                                                              \
        "mma.sync.aligned.m16n8k16.row.col.f32.f16.f16.f32 "                   \
        "{%0,%1,%2,%3}, {%4,%5,%6,%7}, {%8,%9}, {%0,%1,%2,%3};"                \
        : "+f"((c)[0]), "+f"((c)[1]), "+f"((c)[2]), "+f"((c)[3])               \
        : "r"((a)[0]), "r"((a)[1]), "r"((a)[2]), "r"((a)[3]),                  \
          "r"((b)[0]), "r"((b)[1]))

#define CP_ASYNC16(dst, src)                                                   \
    asm volatile("cp.async.cg.shared.global [%0], [%1], 16;"                   \
                 :: "r"(dst), "l"(src) : "memory")
#define CP_COMMIT() asm volatile("cp.async.commit_group;" ::: "memory")
#define CP_WAIT(n) asm volatile("cp.async.wait_group %0;" :: "n"(n) : "memory")

// fp16 hi/lo split of a float pair
__device__ __forceinline__ void split2h(float x, float y, uint32_t& hi,
                                        uint32_t& lo) {
    __half hx = __float2half_rn(x), hy = __float2half_rn(y);
    __half lx = __float2half_rn(x - __half2float(hx));
    __half ly = __float2half_rn(y - __half2float(hy));
    __half2 h2 = __halves2half2(hx, hy);
    __half2 l2 = __halves2half2(lx, ly);
    hi = *(uint32_t*)&h2;
    lo = *(uint32_t*)&l2;
}

// ---------------------------------------------------------------------------
// fp32 -> (fp16 hi, fp16 lo) split, 4 elems/thread
// ---------------------------------------------------------------------------
__global__ void split_h_kernel(const float4* __restrict__ src,
                               __half2* __restrict__ hi,
                               __half2* __restrict__ lo, int n4) {
    int i = blockIdx.x * blockDim.x + threadIdx.x;
    if (i >= n4) return;
    float4 x = src[i];
    uint32_t h0, l0, h1, l1;
    split2h(x.x, x.y, h0, l0);
    split2h(x.z, x.w, h1, l1);
    ((uint32_t*)hi)[2 * i] = h0;
    ((uint32_t*)hi)[2 * i + 1] = h1;
    ((uint32_t*)lo)[2 * i] = l0;
    ((uint32_t*)lo)[2 * i + 1] = l1;
}

// fp32 -> fp16 convert, 4 elems/thread
__global__ void conv_h_kernel(const float4* __restrict__ src,
                              __half2* __restrict__ dst, int n4) {
    int i = blockIdx.x * blockDim.x + threadIdx.x;
    if (i >= n4) return;
    float4 x = src[i];
    dst[2 * i] = __halves2half2(__float2half_rn(x.x), __float2half_rn(x.y));
    dst[2 * i + 1] = __halves2half2(__float2half_rn(x.z), __float2half_rn(x.w));
}

// ---------------------------------------------------------------------------
// fp16x2 HMMA GEMM v5 (frozen from R16)
// ---------------------------------------------------------------------------
#define SROW2 80
#define TILE2 (128 * SROW2)
#define STAGE5 (3 * TILE2)
#define GEMM5_SMEM (2 * STAGE5)

template <int N, int K>
__global__ __launch_bounds__(128) void gemm_hmma5(
    const __half* __restrict__ a_hi, const __half* __restrict__ a_lo,
    const __half* __restrict__ w_h, float* __restrict__ C) {
    constexpr int NCH = K / 32;

    extern __shared__ __align__(16) char sm2[];
    const uint32_t sb = smem_u32(sm2);

    const int tid = threadIdx.x;
    const int lane = tid & 31;
    const int warp = tid >> 5;
    const int wm = warp >> 1;
    const int wn = warp & 1;
    const int m0 = blockIdx.y * 128;
    const int n0 = blockIdx.x * 128;

    auto stage_load = [&](int buf, int kk) {
        const uint32_t dst = sb + buf * STAGE5;
#pragma unroll
        for (int i = 0; i < 4; i++) {
            int lin = tid + i * 128;
            int row = lin >> 2;
            int c16 = lin & 3;
            uint32_t so = (uint32_t)row * SROW2 + c16 * 16;
            size_t ga = (size_t)(m0 + row) * K + kk + c16 * 8;
            size_t gw = (size_t)(n0 + row) * K + kk + c16 * 8;
            CP_ASYNC16(dst + 0 * TILE2 + so, a_hi + ga);
            CP_ASYNC16(dst + 1 * TILE2 + so, a_lo + ga);
            CP_ASYNC16(dst + 2 * TILE2 + so, w_h + gw);
        }
    };

    float acc[4][8][4];
#pragma unroll
    for (int t = 0; t < 4; t++)
#pragma unroll
        for (int n = 0; n < 8; n++)
#pragma unroll
            for (int j = 0; j < 4; j++) acc[t][n][j] = 0.0f;

    const uint32_t a_row = (uint32_t)(wm * 64 + ((lane >> 3) & 1) * 8 + (lane & 7));
    const uint32_t a_cb = (uint32_t)((lane >> 4) & 1) * 16;
    const uint32_t b_row = (uint32_t)(wn * 64 + ((lane >> 4) & 1) * 8 + (lane & 7));
    const uint32_t b_cb = (uint32_t)((lane >> 3) & 1) * 16;

    stage_load(0, 0);
    CP_COMMIT();

#pragma unroll 1
    for (int c = 0; c < NCH; c++) {
        if (c + 1 < NCH) {
            stage_load((c + 1) & 1, (c + 1) * 32);
            CP_COMMIT();
            CP_WAIT(1);
        } else {
            CP_WAIT(0);
        }
        __syncthreads();

        const uint32_t st = sb + (c & 1) * STAGE5;
        const uint32_t sAhi = st, sAlo = st + TILE2;
        const uint32_t sW = st + 2 * TILE2;

#pragma unroll
        for (int k16 = 0; k16 < 2; k16++) {
            const uint32_t kb = (uint32_t)k16 * 32;
            uint32_t ah[4][4], al[4][4];
#pragma unroll
            for (int t = 0; t < 4; t++) {
                LDSM_X4(ah[t][0], ah[t][1], ah[t][2], ah[t][3],
                        sAhi + (a_row + t * 16) * SROW2 + kb + a_cb);
                LDSM_X4(al[t][0], al[t][1], al[t][2], al[t][3],
                        sAlo + (a_row + t * 16) * SROW2 + kb + a_cb);
            }
            uint32_t bh[8][2];
#pragma unroll
            for (int p = 0; p < 4; p++) {
                uint32_t r0, r1, r2, r3;
                LDSM_X4(r0, r1, r2, r3,
                        sW + (b_row + p * 16) * SROW2 + kb + b_cb);
                bh[2 * p][0] = r0; bh[2 * p][1] = r1;
                bh[2 * p + 1][0] = r2; bh[2 * p + 1][1] = r3;
            }
#pragma unroll
            for (int t = 0; t < 4; t++)
#pragma unroll
                for (int n = 0; n < 8; n++) MMAF16(acc[t][n], ah[t], bh[n]);
#pragma unroll
            for (int t = 0; t < 4; t++)
#pragma unroll
                for (int n = 0; n < 8; n++) MMAF16(acc[t][n], al[t], bh[n]);
        }
        __syncthreads();
    }

#pragma unroll
    for (int t = 0; t < 4; t++) {
        int r0 = m0 + wm * 64 + t * 16 + (lane >> 2);
#pragma unroll
        for (int n = 0; n < 8; n++) {
            int col = n0 + wn * 64 + n * 8 + (lane & 3) * 2;
            *(float2*)&C[(size_t)r0 * N + col] = make_float2(acc[t][n][0], acc[t][n][1]);
            *(float2*)&C[(size_t)(r0 + 8) * N + col] = make_float2(acc[t][n][2], acc[t][n][3]);
        }
    }
}

// ---------------------------------------------------------------------------
// Position read: robust to int32 vs int64 storage of position_ids (arange).
// ---------------------------------------------------------------------------
__device__ __forceinline__ int read_pos(const int* __restrict__ pos32, int n) {
    bool is64 = (pos32[1] == 0);
    return pos32[is64 ? 2 * n : n];
}

// RoPE + scatter: Q -> fp16 hi/lo
__global__ void rope_q_kernel(const int* __restrict__ pos32) {
    int idx = blockIdx.x * blockDim.x + threadIdx.x;
    int d = idx & 63;
    int h = (idx >> 6) & (NHEAD - 1);
    int s = (idx >> 10) & (SEQ - 1);
    int b = idx >> 21;

    int p = read_pos(pos32, b * SEQ + s);
    float invf = (float)exp(-((double)d / 64.0) * 9.210340371976184);
    float ang = (float)p * invf;
    float sn, c;
    sincosf(ang, &sn, &c);

    const float* src = g_qkv + ((size_t)b * SEQ + s) * QKVN + h * HDIM;
    float x1 = src[d], x2 = src[d + 64];
    float y1 = x1 * c - x2 * sn;
    float y2 = x2 * c + x1 * sn;

    size_t o = (((size_t)(b * NHEAD + h)) * SEQ + s) * HDIM;
    __half h1 = __float2half_rn(y1);
    __half h2 = __float2half_rn(y2);
    g_q_hi[o + d] = h1;
    g_q_hi[o + d + 64] = h2;
    g_q_lo[o + d] = __float2half_rn(y1 - __half2float(h1));
    g_q_lo[o + d + 64] = __float2half_rn(y2 - __half2float(h2));
}

// RoPE + scatter: K -> single fp16
__global__ void rope_k_kernel(const int* __restrict__ pos32) {
    int idx = blockIdx.x * blockDim.x + threadIdx.x;
    int d = idx & 63;
    int h = (idx >> 6) & (NKVH - 1);
    int s = (idx >> 8) & (SEQ - 1);
    int b = idx >> 19;

    int p = read_pos(pos32, b * SEQ + s);
    float invf = (float)exp(-((double)d / 64.0) * 9.210340371976184);
    float ang = (float)p * invf;
    float sn, c;
    sincosf(ang, &sn, &c);

    const float* src = g_qkv + ((size_t)b * SEQ + s) * QKVN + HIDN + h * HDIM;
    float x1 = src[d], x2 = src[d + 64];
    float y1 = x1 * c - x2 * sn;
    float y2 = x2 * c + x1 * sn;

    size_t o = (((size_t)(b * NKVH + h)) * SEQ + s) * HDIM;
    g_k_h[o + d] = __float2half_rn(y1);
    g_k_h[o + d + 64] = __float2half_rn(y2);
}

// ---------------------------------------------------------------------------
// V fp16 + transpose to [b][hk][d][SEQ].
// ---------------------------------------------------------------------------
__global__ void vt_split_kernel() {
    __shared__ __half th[32][72];
    const int s0 = blockIdx.x * 64;
    const int hk = blockIdx.y >> 2;
    const int d0 = (blockIdx.y & 3) * 32;
    const int b = blockIdx.z;
    const int t = threadIdx.x;

#pragma unroll
    for (int i = 0; i < 8; i++) {
        int s = (t >> 5) + i * 8;
        int d = t & 31;
        float x = g_qkv[((size_t)b * SEQ + s0 + s) * QKVN + HIDN + NKVH * HDIM +
                        hk * HDIM + d0 + d];
        th[d][s] = __float2half_rn(x);
    }
    __syncthreads();

    int d = t >> 3, c8 = (t & 7) * 8;
    size_t o = (((size_t)(b * NKVH + hk)) * HDIM + d0 + d) * SEQ + s0 + c8;
    *(uint4*)(g_vt_h + o) = *(uint4*)&th[d][c8];
}

// ---------------------------------------------------------------------------
// Flash attention: QK^T fp16x2 (Q hi/lo x K single) + PV fp16x2.
// Pipelined K/V loads; K ping-pongs between its region and the dead Q-hi
// region. Epilogue emits fp16 hi/lo ctx.
// ---------------------------------------------------------------------------
#define QS_STR 272
#define VT_STR 144
#define ATTN_SMEM (3 * 64 * QS_STR + 128 * VT_STR) /* 70656 */

__global__ __launch_bounds__(128, 2) void attn_hmma() {
    extern __shared__ __align__(16) char smr[];
    const uint32_t sbase = smem_u32(smr);
    const uint32_t sQhi = sbase;                    // Q hi, then K stage 1
    const uint32_t sQlo = sQhi + 64 * QS_STR;       // Q lo (dead after frags)
    const uint32_t sK0 = sQlo + 64 * QS_STR;        // K stage 0
    const uint32_t sVh = sK0 + 64 * QS_STR;         // V (fp16 single)

    const int tid = threadIdx.x;
    const int lane = tid & 31;
    const int wm = tid >> 5;
    const int qb = gridDim.x - 1 - blockIdx.x; // heaviest first
    const int h = blockIdx.y;
    const int b = blockIdx.z;
    const int q0 = qb * 64;
    const int hk = h / NREP;

    const __half* Qhig = g_q_hi + (((size_t)(b * NHEAD + h)) * SEQ + q0) * HDIM;
    const __half* Qlog = g_q_lo + (((size_t)(b * NHEAD + h)) * SEQ + q0) * HDIM;
    const __half* Khg = g_k_h + ((size_t)(b * NKVH + hk)) * SEQ * HDIM;
    const __half* Vthg = g_vt_h + ((size_t)(b * NKVH + hk)) * HDIM * SEQ;

    auto load_k = [&](uint32_t dst, int k0) {
#pragma unroll
        for (int i = 0; i < 8; i++) {
            int lin = tid + i * 128;
            int row = lin >> 4, c = lin & 15;
            uint32_t so = (uint32_t)row * QS_STR + c * 16;
            size_t go = (size_t)(k0 + row) * HDIM + c * 8;
            CP_ASYNC16(dst + so, Khg + go);
        }
    };
    auto load_v = [&](int k0) {
#pragma unroll
        for (int i = 0; i < 8; i++) {
            int lin = tid + i * 128;
            int row = lin >> 3, c = lin & 7;
            uint32_t so = (uint32_t)row * VT_STR + c * 16;
            size_t go = (size_t)row * SEQ + k0 + c * 8;
            CP_ASYNC16(sVh + so, Vthg + go);
        }
    };

    // prologue: group0 = Q tiles, group1 = K0 + V0
#pragma unroll
    for (int i = 0; i < 8; i++) {
        int lin = tid + i * 128;
        int row = lin >> 4, c = lin & 15;
        uint32_t so = (uint32_t)row * QS_STR + c * 16;
        size_t go = (size_t)row * HDIM + c * 8;
        CP_ASYNC16(sQhi + so, Qhig + go);
        CP_ASYNC16(sQlo + so, Qlog + go);
    }
    CP_COMMIT();
    load_k(sK0, 0);
    load_v(0);
    CP_COMMIT();

    CP_WAIT(1);
    __syncthreads();

    const uint32_t a_row = (uint32_t)(wm * 16 + ((lane >> 3) & 1) * 8 + (lane & 7));
    const uint32_t a_cb = (uint32_t)((lane >> 4) & 1) * 16;
    const uint32_t b_row = (uint32_t)(((lane >> 4) & 1) * 8 + (lane & 7));
    const uint32_t b_cb = (uint32_t)((lane >> 3) & 1) * 16;

    uint32_t qhi[8][4], qlo[8][4];
#pragma unroll
    for (int k16 = 0; k16 < 8; k16++) {
        LDSM_X4(qhi[k16][0], qhi[k16][1], qhi[k16][2], qhi[k16][3],
                sQhi + a_row * QS_STR + k16 * 32 + a_cb);
        LDSM_X4(qlo[k16][0], qlo[k16][1], qlo[k16][2], qlo[k16][3],
                sQlo + a_row * QS_STR + k16 * 32 + a_cb);
    }
    __syncthreads(); // Q-hi region becomes K stage 1

    float o[16][4];
#pragma unroll
    for (int n = 0; n < 16; n++)
#pragma unroll
        for (int j = 0; j < 4; j++) o[n][j] = 0.0f;
    float m0r = -FLT_MAX, m1r = -FLT_MAX, l0 = 0.0f, l1 = 0.0f;

    const float scale = 0.08838834764831845f;
    const int rowg0 = q0 + wm * 16 + (lane >> 2);
    const int rowg1 = rowg0 + 8;

#pragma unroll 1
    for (int kt = 0; kt <= qb; kt++) {
        if (kt == 0) { CP_WAIT(0); } else { CP_WAIT(1); }
        __syncthreads();

        const uint32_t kcur = (kt & 1) ? sQhi : sK0;

        // ---- S = Q K^T (fp16x2: qhi*k + qlo*k) ----
        float s[8][4];
#pragma unroll
        for (int n = 0; n < 8; n++)
#pragma unroll
            for (int j = 0; j < 4; j++) s[n][j] = 0.0f;

#pragma unroll
        for (int k16 = 0; k16 < 8; k16++) {
            uint32_t bh[8][2];
#pragma unroll
            for (int p = 0; p < 4; p++) {
                uint32_t r0, r1, r2, r3;
                LDSM_X4(r0, r1, r2, r3,
                        kcur + (p * 16 + b_row) * QS_STR + k16 * 32 + b_cb);
                bh[2 * p][0] = r0; bh[2 * p][1] = r1;
                bh[2 * p + 1][0] = r2; bh[2 * p + 1][1] = r3;
            }
#pragma unroll
            for (int n = 0; n < 8; n++) MMAF16(s[n], qhi[k16], bh[n]);
#pragma unroll
            for (int n = 0; n < 8; n++) MMAF16(s[n], qlo[k16], bh[n]);
        }

        // prefetch K(kt+1) into alternate stage
        if (kt < qb) {
            load_k((kt & 1) ? sK0 : sQhi, (kt + 1) * 64);
            CP_COMMIT();
        }

        // ---- scale + causal mask ----
#pragma unroll
        for (int n = 0; n < 8; n++)
#pragma unroll
            for (int j = 0; j < 4; j++) s[n][j] *= scale;
        if (kt == qb) {
            const int colb = kt * 64 + (lane & 3) * 2;
#pragma unroll
            for (int n = 0; n < 8; n++) {
#pragma unroll
                for (int e = 0; e < 2; e++) {
                    int col = colb + n * 8 + e;
                    if (col > rowg0) s[n][e] = -1e30f;
                    if (col > rowg1) s[n][2 + e] = -1e30f;
                }
            }
        }

        // ---- online softmax ----
        float mx0 = -FLT_MAX, mx1 = -FLT_MAX;
#pragma unroll
        for (int n = 0; n < 8; n++) {
            mx0 = fmaxf(mx0, fmaxf(s[n][0], s[n][1]));
            mx1 = fmaxf(mx1, fmaxf(s[n][2], s[n][3]));
        }
        mx0 = fmaxf(mx0, __shfl_xor_sync(0xffffffffu, mx0, 1));
        mx0 = fmaxf(mx0, __shfl_xor_sync(0xffffffffu, mx0, 2));
        mx1 = fmaxf(mx1, __shfl_xor_sync(0xffffffffu, mx1, 1));
        mx1 = fmaxf(mx1, __shfl_xor_sync(0xffffffffu, mx1, 2));
        float mn0 = fmaxf(m0r, mx0), mn1 = fmaxf(m1r, mx1);
        float corr0 = __expf(m0r - mn0), corr1 = __expf(m1r - mn1);
        m0r = mn0; m1r = mn1;

        float rs0 = 0.0f, rs1 = 0.0f;
#pragma unroll
        for (int n = 0; n < 8; n++) {
            s[n][0] = __expf(s[n][0] - mn0);
            s[n][1] = __expf(s[n][1] - mn0);
            s[n][2] = __expf(s[n][2] - mn1);
            s[n][3] = __expf(s[n][3] - mn1);
            rs0 += s[n][0] + s[n][1];
            rs1 += s[n][2] + s[n][3];
        }
        rs0 += __shfl_xor_sync(0xffffffffu, rs0, 1);
        rs0 += __shfl_xor_sync(0xffffffffu, rs0, 2);
        rs1 += __shfl_xor_sync(0xffffffffu, rs1, 1);
        rs1 += __shfl_xor_sync(0xffffffffu, rs1, 2);
        l0 = l0 * corr0 + rs0;
        l1 = l1 * corr1 + rs1;

#pragma unroll
        for (int n = 0; n < 16; n++) {
            o[n][0] *= corr0; o[n][1] *= corr0;
            o[n][2] *= corr1; o[n][3] *= corr1;
        }

        if (kt < qb) { CP_WAIT(1); } else { CP_WAIT(0); }
        __syncthreads();

        // ---- O += P V : P fp16 hi/lo x V fp16 ----
#pragma unroll
        for (int j = 0; j < 4; j++) {
            uint32_t ah[4], al[4];
            split2h(s[2 * j][0], s[2 * j][1], ah[0], al[0]);
            split2h(s[2 * j][2], s[2 * j][3], ah[1], al[1]);
            split2h(s[2 * j + 1][0], s[2 * j + 1][1], ah[2], al[2]);
            split2h(s[2 * j + 1][2], s[2 * j + 1][3], ah[3], al[3]);
#pragma unroll
            for (int p = 0; p < 8; p++) {
                uint32_t r0, r1, r2, r3;
                LDSM_X4(r0, r1, r2, r3,
                        sVh + (p * 16 + b_row) * VT_STR + j * 32 + b_cb);
                uint32_t bh0[2] = {r0, r1}, bh1[2] = {r2, r3};
                MMAF16(o[2 * p], ah, bh0);
                MMAF16(o[2 * p + 1], ah, bh1);
                MMAF16(o[2 * p], al, bh0);
                MMAF16(o[2 * p + 1], al, bh1);
            }
        }

        __syncthreads();
        if (kt < qb) {
            load_v((kt + 1) * 64);
            CP_COMMIT();
        }
    }

    // ---- epilogue: normalize, fp16 hi/lo split, write [b, s, h, d] ----
    float linv0 = 1.0f / l0, linv1 = 1.0f / l1;
    size_t base0 = (((size_t)b * SEQ + rowg0) * NHEAD + h) * HDIM + (lane & 3) * 2;
    size_t base1 = (((size_t)b * SEQ + rowg1) * NHEAD + h) * HDIM + (lane & 3) * 2;
#pragma unroll
    for (int n = 0; n < 16; n++) {
        uint32_t hi, lo;
        split2h(o[n][0] * linv0, o[n][1] * linv0, hi, lo);
        *(uint32_t*)(g_ctx_hi + base0 + n * 8) = hi;
        *(uint32_t*)(g_ctx_lo + base0 + n * 8) = lo;
        split2h(o[n][2] * linv1, o[n][3] * linv1, hi, lo);
        *(uint32_t*)(g_ctx_hi + base1 + n * 8) = hi;
        *(uint32_t*)(g_ctx_lo + base1 + n * 8) = lo;
    }
}

// ---------------------------------------------------------------------------
extern "C" void kernel_launch(void* const* d_in, const int* in_sizes, int n_in,
                              void* d_out, int out_size) {
    const float* hs = (const float*)d_in[0];
    const float* w_qkv = (const float*)d_in[1];
    const float* w_out = (const float*)d_in[2];
    const int* pos32 = (const int*)d_in[4];
    float* out = (float*)d_out;

    float* qkv;
    __half *hs_hi, *hs_lo, *wq_h, *wo_h, *cx_hi, *cx_lo;
    cudaGetSymbolAddress((void**)&qkv, g_qkv);
    cudaGetSymbolAddress((void**)&hs_hi, g_hs_hi);
    cudaGetSymbolAddress((void**)&hs_lo, g_hs_lo);
    cudaGetSymbolAddress((void**)&wq_h, g_wqkv_h);
    cudaGetSymbolAddress((void**)&wo_h, g_wout_h);
    cudaGetSymbolAddress((void**)&cx_hi, g_ctx_hi);
    cudaGetSymbolAddress((void**)&cx_lo, g_ctx_lo);

    cudaFuncSetAttribute(gemm_hmma5<QKVN, HIDN>,
                         cudaFuncAttributeMaxDynamicSharedMemorySize, GEMM5_SMEM);
    cudaFuncSetAttribute(gemm_hmma5<HIDN, HIDN>,
                         cudaFuncAttributeMaxDynamicSharedMemorySize, GEMM5_SMEM);
    cudaFuncSetAttribute(attn_hmma, cudaFuncAttributeMaxDynamicSharedMemorySize,
                         ATTN_SMEM);

    // 0. fp16 operand prep
    {
        int n4;
        n4 = (MROWS * HIDN) / 4;
        split_h_kernel<<<(n4 + 255) / 256, 256>>>((const float4*)hs,
                                                  (__half2*)hs_hi,
                                                  (__half2*)hs_lo, n4);
        n4 = (QKVN * HIDN) / 4;
        conv_h_kernel<<<(n4 + 255) / 256, 256>>>((const float4*)w_qkv,
                                                 (__half2*)wq_h, n4);
        n4 = (HIDN * HIDN) / 4;
        conv_h_kernel<<<(n4 + 255) / 256, 256>>>((const float4*)w_out,
                                                 (__half2*)wo_h, n4);
    }

    // 1. QKV GEMM (HMMA fp16x2)
    {
        dim3 grid(QKVN / 128, MROWS / 128);
        gemm_hmma5<QKVN, HIDN><<<grid, 128, GEMM5_SMEM>>>(hs_hi, hs_lo, wq_h,
                                                          qkv);
    }

    // 2. RoPE + scatter (Q fp16 hi/lo, K fp16); V fp16 transpose
    rope_q_kernel<<<(BSZ * SEQ * NHEAD * 64) / 256, 256>>>(pos32);
    rope_k_kernel<<<(BSZ * SEQ * NKVH * 64) / 256, 256>>>(pos32);
    {
        dim3 grid(SEQ / 64, (HDIM / 32) * NKVH, BSZ);
        vt_split_kernel<<<grid, 256>>>();
    }

    // 3. Flash attention (QK fp16x2, PV fp16x2, pipelined K/V)
    {
        dim3 grid(SEQ / 64, NHEAD, BSZ);
        attn_hmma<<<grid, 128, ATTN_SMEM>>>();
    }

    // 4. Output GEMM (HMMA fp16x2)
    {
        dim3 grid(HIDN / 128, MROWS / 128);
        gemm_hmma5<HIDN, HIDN><<<grid, 128, GEMM5_SMEM>>>(cx_hi, cx_lo, wo_h,
                                                          out);
    }
}